// round 3
// baseline (speedup 1.0000x reference)
#include <cuda_runtime.h>
#include <math.h>

#define S_LEN   2048
#define BATCH   2
#define HID     2048
#define NHEADS  32
#define KVHEADS 8
#define HDIM    64

// ---------------- scratch (static device globals; no allocations) ----------
__device__ float g_q[(size_t)BATCH * S_LEN * HID];                 // 33.5 MB
__device__ float g_k[(size_t)BATCH * S_LEN * KVHEADS * HDIM];      //  8.4 MB
__device__ float g_v[(size_t)BATCH * S_LEN * KVHEADS * HDIM];      //  8.4 MB
__device__ float g_attn[(size_t)BATCH * S_LEN * HID];              // 33.5 MB

// ============================================================================
// SGEMM:  C[M,N] = A[M,K] * B[N,K]^T      (A, B, C row-major, fp32)
// 128x128 block tile, K-tile 16, 256 threads, 8x8 micro-tile per thread.
// ============================================================================
#define GBM 128
#define GBN 128
#define GBK 16
#define GPAD 132   // row padding (floats): keeps float4 alignment, breaks banks

__global__ __launch_bounds__(256) void sgemm_nt(
    const float* __restrict__ A, const float* __restrict__ B,
    float* __restrict__ C, int M, int N, int K)
{
    __shared__ float As[GBK][GPAD];   // As[k][m]
    __shared__ float Bs[GBK][GPAD];   // Bs[k][n]

    const int tid = threadIdx.x;
    const int bm  = blockIdx.y * GBM;
    const int bn  = blockIdx.x * GBN;

    const int lr = tid >> 2;           // 0..63 (tile row for loads)
    const int lc = (tid & 3) << 2;     // 0,4,8,12 (k offset for loads)

    const int ty = tid >> 4;           // 0..15
    const int tx = tid & 15;           // 0..15

    float acc[8][8];
#pragma unroll
    for (int i = 0; i < 8; ++i)
#pragma unroll
        for (int j = 0; j < 8; ++j) acc[i][j] = 0.f;

    for (int k0 = 0; k0 < K; k0 += GBK) {
        float4 a0 = *(const float4*)(A + (size_t)(bm + lr)      * K + k0 + lc);
        float4 a1 = *(const float4*)(A + (size_t)(bm + lr + 64) * K + k0 + lc);
        As[lc + 0][lr] = a0.x; As[lc + 1][lr] = a0.y;
        As[lc + 2][lr] = a0.z; As[lc + 3][lr] = a0.w;
        As[lc + 0][lr + 64] = a1.x; As[lc + 1][lr + 64] = a1.y;
        As[lc + 2][lr + 64] = a1.z; As[lc + 3][lr + 64] = a1.w;

        float4 b0 = *(const float4*)(B + (size_t)(bn + lr)      * K + k0 + lc);
        float4 b1 = *(const float4*)(B + (size_t)(bn + lr + 64) * K + k0 + lc);
        Bs[lc + 0][lr] = b0.x; Bs[lc + 1][lr] = b0.y;
        Bs[lc + 2][lr] = b0.z; Bs[lc + 3][lr] = b0.w;
        Bs[lc + 0][lr + 64] = b1.x; Bs[lc + 1][lr + 64] = b1.y;
        Bs[lc + 2][lr + 64] = b1.z; Bs[lc + 3][lr + 64] = b1.w;

        __syncthreads();

#pragma unroll
        for (int kk = 0; kk < GBK; ++kk) {
            float4 ra0 = *(const float4*)&As[kk][ty * 8];
            float4 ra1 = *(const float4*)&As[kk][ty * 8 + 4];
            float4 rb0 = *(const float4*)&Bs[kk][tx * 8];
            float4 rb1 = *(const float4*)&Bs[kk][tx * 8 + 4];
            float ra[8] = {ra0.x, ra0.y, ra0.z, ra0.w, ra1.x, ra1.y, ra1.z, ra1.w};
            float rb[8] = {rb0.x, rb0.y, rb0.z, rb0.w, rb1.x, rb1.y, rb1.z, rb1.w};
#pragma unroll
            for (int i = 0; i < 8; ++i)
#pragma unroll
                for (int j = 0; j < 8; ++j)
                    acc[i][j] += ra[i] * rb[j];
        }
        __syncthreads();
    }

#pragma unroll
    for (int i = 0; i < 8; ++i) {
        float* crow = C + (size_t)(bm + ty * 8 + i) * N + bn + tx * 8;
        float4 c0 = {acc[i][0], acc[i][1], acc[i][2], acc[i][3]};
        float4 c1 = {acc[i][4], acc[i][5], acc[i][6], acc[i][7]};
        *(float4*)(crow)     = c0;
        *(float4*)(crow + 4) = c1;
    }
}

// ============================================================================
// RoPE (in place on q_buf [4096][2048] and k_buf [4096][512])
// pair d in [0,32): new[d]    = x[d]*cos - x[d+32]*sin
//                   new[d+32] = x[d+32]*cos + x[d]*sin
// cos/sin of angle = pos * base^(-d/32)
// ============================================================================
__global__ void rope_kernel(float* __restrict__ qb, float* __restrict__ kb)
{
    const int TOT = BATCH * S_LEN * (NHEADS + KVHEADS) * (HDIM / 2);
    int t = blockIdx.x * blockDim.x + threadIdx.x;
    if (t >= TOT) return;

    int pair = t & 31;
    int rest = t >> 5;
    int head = rest % (NHEADS + KVHEADS);
    int row  = rest / (NHEADS + KVHEADS);
    int pos  = row & (S_LEN - 1);

    // inv_freq = 10000^(-pair/32), computed in double for accuracy
    float inv = (float)exp(-(double)pair * (9.210340371976184 / 32.0));
    float ang = (float)pos * inv;
    float sv, cv;
    sincosf(ang, &sv, &cv);

    float* base;
    if (head < NHEADS) base = qb + (size_t)row * HID + head * HDIM;
    else               base = kb + (size_t)row * (KVHEADS * HDIM) + (head - NHEADS) * HDIM;

    float x0 = base[pair];
    float x1 = base[pair + 32];
    base[pair]      = x0 * cv - x1 * sv;
    base[pair + 32] = x1 * cv + x0 * sv;
}

// ============================================================================
// Flash attention, fp32, causal.  64-query x 64-key tiles, online softmax.
// grid = (S/64, NHEADS, BATCH), block = 256.
// Thread maps:
//   scores: (tr,tc) 16x16 thread grid, 4x4 scores each
//   softmax/PV: row = tid/4, 16 output dims per thread
// Warp w owns score/softmax rows 8w..8w+7 in BOTH phases -> __syncwarp only.
// ============================================================================
__global__ __launch_bounds__(256) void attn_kernel(
    const float* __restrict__ q, const float* __restrict__ k,
    const float* __restrict__ v, float* __restrict__ o)
{
    extern __shared__ float sm[];
    float* Qs = sm;                 // [64][65]
    float* Ks = sm + 64 * 65;       // [64][65]
    float* Vs = sm + 2 * 64 * 65;   // [64][65]
    float* Ss = sm + 3 * 64 * 65;   // [64][65]

    const int qt  = blockIdx.x;
    const int h   = blockIdx.y;
    const int b   = blockIdx.z;
    const int kvh = h >> 2;
    const int q0  = qt << 6;
    const int tid = threadIdx.x;

    // load Q tile [64][64]
    for (int i = tid; i < 1024; i += 256) {
        int r  = i >> 4;
        int d4 = (i & 15) << 2;
        float4 t4 = *(const float4*)(q + (size_t)(b * S_LEN + q0 + r) * HID + h * HDIM + d4);
        float* dst = Qs + r * 65 + d4;
        dst[0] = t4.x; dst[1] = t4.y; dst[2] = t4.z; dst[3] = t4.w;
    }

    const int tr  = (tid >> 4) << 2;    // score row base (0..60)
    const int tc  = (tid & 15) << 2;    // score col base (0..60)
    const int row = tid >> 2;           // softmax/PV row (0..63)
    const int c0  = (tid & 3) << 4;     // 16-wide column/dim segment

    float oacc[16];
#pragma unroll
    for (int i = 0; i < 16; ++i) oacc[i] = 0.f;
    float m_i = -INFINITY, l_i = 0.f;

    __syncthreads();

    for (int kt = 0; kt <= qt; ++kt) {
        const int k0 = kt << 6;

        // load K,V tiles [64][64]
        for (int i = tid; i < 1024; i += 256) {
            int r  = i >> 4;
            int d4 = (i & 15) << 2;
            size_t g = (size_t)(b * S_LEN + k0 + r) * (KVHEADS * HDIM) + kvh * HDIM + d4;
            float4 k4 = *(const float4*)(k + g);
            float4 v4 = *(const float4*)(v + g);
            float* kd = Ks + r * 65 + d4;
            kd[0] = k4.x; kd[1] = k4.y; kd[2] = k4.z; kd[3] = k4.w;
            float* vd = Vs + r * 65 + d4;
            vd[0] = v4.x; vd[1] = v4.y; vd[2] = v4.z; vd[3] = v4.w;
        }
        __syncthreads();

        // ---- scores: S = Q K^T (4x4 per thread) ----
        float sc[4][4];
#pragma unroll
        for (int i = 0; i < 4; ++i)
#pragma unroll
            for (int j = 0; j < 4; ++j) sc[i][j] = 0.f;

#pragma unroll 8
        for (int d = 0; d < 64; ++d) {
            float qa[4], kb4[4];
#pragma unroll
            for (int i = 0; i < 4; ++i) qa[i]  = Qs[(tr + i) * 65 + d];
#pragma unroll
            for (int j = 0; j < 4; ++j) kb4[j] = Ks[(tc + j) * 65 + d];
#pragma unroll
            for (int i = 0; i < 4; ++i)
#pragma unroll
                for (int j = 0; j < 4; ++j)
                    sc[i][j] += qa[i] * kb4[j];
        }

#pragma unroll
        for (int i = 0; i < 4; ++i)
#pragma unroll
            for (int j = 0; j < 4; ++j) {
                int qg = q0 + tr + i;
                int kg = k0 + tc + j;
                float sval = sc[i][j] * 0.125f;       // 1/sqrt(64)
                if (kg > qg) sval = -INFINITY;
                Ss[(tr + i) * 65 + tc + j] = sval;
            }
        __syncwarp();

        // ---- online softmax (4 threads per row, 16 cols each) ----
        float* srow = Ss + row * 65;
        float tmax = -INFINITY;
#pragma unroll
        for (int c = 0; c < 16; ++c) tmax = fmaxf(tmax, srow[c0 + c]);
        tmax = fmaxf(tmax, __shfl_xor_sync(0xffffffffu, tmax, 1));
        tmax = fmaxf(tmax, __shfl_xor_sync(0xffffffffu, tmax, 2));

        float m_new = fmaxf(m_i, tmax);
        float corr  = __expf(m_i - m_new);
        float lsum  = 0.f;
#pragma unroll
        for (int c = 0; c < 16; ++c) {
            float p = __expf(srow[c0 + c] - m_new);
            srow[c0 + c] = p;
            lsum += p;
        }
        lsum += __shfl_xor_sync(0xffffffffu, lsum, 1);
        lsum += __shfl_xor_sync(0xffffffffu, lsum, 2);
        l_i = l_i * corr + lsum;
        m_i = m_new;
#pragma unroll
        for (int i = 0; i < 16; ++i) oacc[i] *= corr;
        __syncwarp();

        // ---- O += P V ----
#pragma unroll 4
        for (int c = 0; c < 64; ++c) {
            float p = srow[c];
            const float* vrow = Vs + c * 65 + c0;
#pragma unroll
            for (int dd = 0; dd < 16; ++dd)
                oacc[dd] += p * vrow[dd];
        }
        __syncthreads();
    }

    float invl = 1.f / l_i;
    float* ob = o + (size_t)(b * S_LEN + q0 + row) * HID + h * HDIM + c0;
#pragma unroll
    for (int dd = 0; dd < 16; ++dd) ob[dd] = oacc[dd] * invl;
}

// ============================================================================
// kernel_launch
// inputs: x [2,2048,2048], Wq [2048,2048], Wk [512,2048], Wv [512,2048],
//         Wo [2048,2048]; output [2,2048,2048] fp32
// ============================================================================
extern "C" void kernel_launch(void* const* d_in, const int* in_sizes, int n_in,
                              void* d_out, int out_size)
{
    (void)in_sizes; (void)n_in; (void)out_size;
    const float* x  = (const float*)d_in[0];
    const float* Wq = (const float*)d_in[1];
    const float* Wk = (const float*)d_in[2];
    const float* Wv = (const float*)d_in[3];
    const float* Wo = (const float*)d_in[4];
    float* out = (float*)d_out;

    float *qb, *kb, *vb, *ab;
    cudaGetSymbolAddress((void**)&qb, g_q);
    cudaGetSymbolAddress((void**)&kb, g_k);
    cudaGetSymbolAddress((void**)&vb, g_v);
    cudaGetSymbolAddress((void**)&ab, g_attn);

    const int M = BATCH * S_LEN;           // 4096

    // QKV projections
    sgemm_nt<<<dim3(HID / GBN, M / GBM), 256>>>(x, Wq, qb, M, HID, HID);
    sgemm_nt<<<dim3((KVHEADS * HDIM) / GBN, M / GBM), 256>>>(x, Wk, kb, M, KVHEADS * HDIM, HID);
    sgemm_nt<<<dim3((KVHEADS * HDIM) / GBN, M / GBM), 256>>>(x, Wv, vb, M, KVHEADS * HDIM, HID);

    // RoPE on Q and K
    const int rope_tot = BATCH * S_LEN * (NHEADS + KVHEADS) * (HDIM / 2);
    rope_kernel<<<(rope_tot + 255) / 256, 256>>>(qb, kb);

    // causal GQA flash attention
    static const int ATTN_SMEM = 4 * 64 * 65 * (int)sizeof(float);   // 66,560 B
    cudaFuncSetAttribute(attn_kernel, cudaFuncAttributeMaxDynamicSharedMemorySize, ATTN_SMEM);
    attn_kernel<<<dim3(S_LEN / 64, NHEADS, BATCH), 256, ATTN_SMEM>>>(qb, kb, vb, ab);

    // output projection
    sgemm_nt<<<dim3(HID / GBN, M / GBM), 256>>>(ab, Wo, out, M, HID, HID);
}

// round 5
// speedup vs baseline: 1.2693x; 1.2693x over previous
#include <cuda_runtime.h>
#include <cuda_bf16.h>
#include <math.h>
#include <stdint.h>

#define S_LEN   2048
#define BATCH   2
#define HID     2048
#define NHEADS  32
#define KVHEADS 8
#define HDIM    64
#define MROWS   (BATCH * S_LEN)     // 4096
#define KVDIM   (KVHEADS * HDIM)    // 512

// ---------------- scratch (static device globals; no allocations) ----------
__device__ float g_q   [(size_t)MROWS * HID];
__device__ float g_k   [(size_t)MROWS * KVDIM];
__device__ float g_v   [(size_t)MROWS * KVDIM];
__device__ float g_attn[(size_t)MROWS * HID];

__device__ __nv_bfloat16 g_xh[(size_t)MROWS * HID];
__device__ __nv_bfloat16 g_xl[(size_t)MROWS * HID];
__device__ __nv_bfloat16 g_wqh[(size_t)HID * HID];
__device__ __nv_bfloat16 g_wql[(size_t)HID * HID];
__device__ __nv_bfloat16 g_wkh[(size_t)KVDIM * HID];
__device__ __nv_bfloat16 g_wkl[(size_t)KVDIM * HID];
__device__ __nv_bfloat16 g_wvh[(size_t)KVDIM * HID];
__device__ __nv_bfloat16 g_wvl[(size_t)KVDIM * HID];
__device__ __nv_bfloat16 g_woh[(size_t)HID * HID];
__device__ __nv_bfloat16 g_wol[(size_t)HID * HID];
__device__ __nv_bfloat16 g_ah[(size_t)MROWS * HID];
__device__ __nv_bfloat16 g_al[(size_t)MROWS * HID];

__device__ float g_rc[S_LEN * 32];
__device__ float g_rs[S_LEN * 32];

// ============================================================================
// PTX helpers (plain sm_103-safe: mma.sync / ldmatrix / cp.async only)
// ============================================================================
__device__ __forceinline__ uint32_t smem_to_u32(const void* p) {
    uint32_t a;
    asm("{ .reg .u64 t; cvta.to.shared.u64 t, %1; cvt.u32.u64 %0, t; }"
        : "=r"(a) : "l"(p));
    return a;
}

#define CP_ASYNC16(smem, gmem) \
    asm volatile("cp.async.cg.shared.global [%0], [%1], 16;" \
                 :: "r"(smem), "l"(gmem) : "memory")
#define CP_COMMIT() asm volatile("cp.async.commit_group;" ::: "memory")
#define CP_WAIT(n)  asm volatile("cp.async.wait_group %0;" :: "n"(n) : "memory")

__device__ __forceinline__ void ldsm_x4(uint32_t* r, uint32_t addr) {
    asm volatile("ldmatrix.sync.aligned.m8n8.x4.shared.b16 {%0,%1,%2,%3}, [%4];"
        : "=r"(r[0]), "=r"(r[1]), "=r"(r[2]), "=r"(r[3]) : "r"(addr));
}
__device__ __forceinline__ void ldsm_x2(uint32_t* r, uint32_t addr) {
    asm volatile("ldmatrix.sync.aligned.m8n8.x2.shared.b16 {%0,%1}, [%2];"
        : "=r"(r[0]), "=r"(r[1]) : "r"(addr));
}

// D(f32) += A(bf16) * B(bf16), m16n8k16
__device__ __forceinline__ void mma16816(float* d, const uint32_t* a, const uint32_t* b) {
    asm volatile(
        "mma.sync.aligned.m16n8k16.row.col.f32.bf16.bf16.f32 "
        "{%0,%1,%2,%3}, {%4,%5,%6,%7}, {%8,%9}, {%0,%1,%2,%3};"
        : "+f"(d[0]), "+f"(d[1]), "+f"(d[2]), "+f"(d[3])
        : "r"(a[0]), "r"(a[1]), "r"(a[2]), "r"(a[3]), "r"(b[0]), "r"(b[1]));
}

// ============================================================================
// fp32 -> bf16 hi/lo split
// ============================================================================
__global__ void split_bf16(const float* __restrict__ in,
                           __nv_bfloat16* __restrict__ hi,
                           __nv_bfloat16* __restrict__ lo, int n)
{
    int i = blockIdx.x * blockDim.x + threadIdx.x;
    if (i >= n) return;
    float v = in[i];
    __nv_bfloat16 h = __float2bfloat16(v);
    float r = v - __bfloat162float(h);
    hi[i] = h;
    lo[i] = __float2bfloat16(r);
}

// ============================================================================
// bf16 hi/lo split GEMM via mma.sync:  C[M,N] = A[M,K] @ B[N,K]^T
// 128x128 CTA tile, BK=32, 8 warps (2x4), warp tile 64x32,
// cp.async double-buffered smem, 80B-padded rows (ldmatrix conflict-free).
// ============================================================================
#define BM 128
#define BN 128
#define BK 32
#define ROWB   80                        // bytes per smem row (32 bf16 + 8 pad)
#define ASZ    (128 * ROWB)              // 10240 B per matrix tile
#define STAGE  (4 * ASZ)                 // Ah, Al, Bh, Bl
#define GEMM_SMEM (2 * STAGE)            // 81920 B

__global__ __launch_bounds__(256, 1) void gemm_mma(
    const __nv_bfloat16* __restrict__ Ah, const __nv_bfloat16* __restrict__ Al,
    const __nv_bfloat16* __restrict__ Bh, const __nv_bfloat16* __restrict__ Bl,
    float* __restrict__ C, int M, int N, int K)
{
    extern __shared__ char smem[];
    const uint32_t sbase = smem_to_u32(smem);

    const int tid  = threadIdx.x;
    const int wid  = tid >> 5;
    const int lane = tid & 31;
    const int wm   = wid >> 2;        // 0..1
    const int wn   = wid & 3;         // 0..3
    const int bm   = blockIdx.y * BM;
    const int bn   = blockIdx.x * BN;

    const __nv_bfloat16* gAh = Ah + (size_t)bm * K;
    const __nv_bfloat16* gAl = Al + (size_t)bm * K;
    const __nv_bfloat16* gBh = Bh + (size_t)bn * K;
    const __nv_bfloat16* gBl = Bl + (size_t)bn * K;

    const int NC = K / BK;

    // ---- async stage loader: 128 rows x 32 bf16 (64B) per matrix, 4 matrices
    const int lr  = tid >> 2;                   // row 0..63 (x2 halves)
    const int lsg = tid & 3;                    // 16B segment 0..3
    auto issue = [&](int kc, int buf) {
        const uint32_t sb = sbase + buf * STAGE;
        const size_t kofs = (size_t)kc * BK + lsg * 8;
#pragma unroll
        for (int t = 0; t < 2; ++t) {
            int r = lr + t * 64;
            uint32_t so = (uint32_t)(r * ROWB + lsg * 16);
            size_t g = (size_t)r * K + kofs;
            CP_ASYNC16(sb + so,           gAh + g);
            CP_ASYNC16(sb + ASZ + so,     gAl + g);
            CP_ASYNC16(sb + 2 * ASZ + so, gBh + g);
            CP_ASYNC16(sb + 3 * ASZ + so, gBl + g);
        }
        CP_COMMIT();
    };

    float acc[4][4][4];
#pragma unroll
    for (int i = 0; i < 4; ++i)
#pragma unroll
        for (int j = 0; j < 4; ++j)
#pragma unroll
            for (int c = 0; c < 4; ++c) acc[i][j][c] = 0.f;

    // ldmatrix smem addresses (offsets within a matrix tile)
    const uint32_t a_row = (uint32_t)(wm * 64 + (lane & 15));
    const uint32_t a_colb = (uint32_t)((lane >> 4) * 16);      // 8 elems = 16B
    const uint32_t b_row = (uint32_t)(wn * 32 + (lane & 7));
    const uint32_t b_colb = (uint32_t)(((lane >> 3) & 1) * 16);

    issue(0, 0);

    for (int kt = 0; kt < NC; ++kt) {
        const int buf = kt & 1;
        if (kt + 1 < NC) { issue(kt + 1, buf ^ 1); CP_WAIT(1); }
        else             { CP_WAIT(0); }
        __syncthreads();

        const uint32_t sAh = sbase + buf * STAGE;
        const uint32_t sAl = sAh + ASZ;
        const uint32_t sBh = sAh + 2 * ASZ;
        const uint32_t sBl = sAh + 3 * ASZ;

#pragma unroll
        for (int ks = 0; ks < 2; ++ks) {
            const uint32_t kofs = ks * 32;     // 16 bf16 = 32 bytes

            uint32_t ah[4][4], al[4][4], bb[4][2];
#pragma unroll
            for (int mt = 0; mt < 4; ++mt) {
                uint32_t off = (a_row + mt * 16) * ROWB + a_colb + kofs;
                ldsm_x4(ah[mt], sAh + off);
                ldsm_x4(al[mt], sAl + off);
            }
#pragma unroll
            for (int nt = 0; nt < 4; ++nt) {
                uint32_t off = (b_row + nt * 8) * ROWB + b_colb + kofs;
                ldsm_x2(bb[nt], sBh + off);
            }
            // hh + lh
#pragma unroll
            for (int mt = 0; mt < 4; ++mt)
#pragma unroll
                for (int nt = 0; nt < 4; ++nt) {
                    mma16816(acc[mt][nt], ah[mt], bb[nt]);
                    mma16816(acc[mt][nt], al[mt], bb[nt]);
                }
            // hl
#pragma unroll
            for (int nt = 0; nt < 4; ++nt) {
                uint32_t off = (b_row + nt * 8) * ROWB + b_colb + kofs;
                ldsm_x2(bb[nt], sBl + off);
            }
#pragma unroll
            for (int mt = 0; mt < 4; ++mt)
#pragma unroll
                for (int nt = 0; nt < 4; ++nt)
                    mma16816(acc[mt][nt], ah[mt], bb[nt]);
        }
        __syncthreads();
    }

    // ---- epilogue: fragment -> global
    const int er = lane >> 2;          // 0..7
    const int ec = (lane & 3) * 2;     // 0,2,4,6
#pragma unroll
    for (int mt = 0; mt < 4; ++mt) {
        const int row0 = bm + wm * 64 + mt * 16 + er;
#pragma unroll
        for (int nt = 0; nt < 4; ++nt) {
            const int col = bn + wn * 32 + nt * 8 + ec;
            float2 v0 = {acc[mt][nt][0], acc[mt][nt][1]};
            float2 v1 = {acc[mt][nt][2], acc[mt][nt][3]};
            *(float2*)(C + (size_t)row0 * N + col)       = v0;
            *(float2*)(C + (size_t)(row0 + 8) * N + col) = v1;
        }
    }
}

// ============================================================================
// RoPE: precomputed cos/sin table + apply
// ============================================================================
__global__ void rope_table(float* __restrict__ ct, float* __restrict__ st)
{
    int t = blockIdx.x * blockDim.x + threadIdx.x;
    if (t >= S_LEN * 32) return;
    int pos  = t >> 5;
    int pair = t & 31;
    float inv = (float)exp(-(double)pair * (9.210340371976184 / 32.0));
    float a = (float)pos * inv;
    float s, c;
    sincosf(a, &s, &c);
    ct[t] = c;
    st[t] = s;
}

__global__ void rope_apply(float* __restrict__ qb, float* __restrict__ kb,
                           const float* __restrict__ ct, const float* __restrict__ st)
{
    const int TOT = MROWS * (NHEADS + KVHEADS) * 32;
    int t = blockIdx.x * blockDim.x + threadIdx.x;
    if (t >= TOT) return;

    int pair = t & 31;
    int rest = t >> 5;
    int head = rest % (NHEADS + KVHEADS);
    int row  = rest / (NHEADS + KVHEADS);
    int pos  = row & (S_LEN - 1);

    float cv = ct[pos * 32 + pair];
    float sv = st[pos * 32 + pair];

    float* base;
    if (head < NHEADS) base = qb + (size_t)row * HID + head * HDIM;
    else               base = kb + (size_t)row * KVDIM + (head - NHEADS) * HDIM;

    float x0 = base[pair];
    float x1 = base[pair + 32];
    base[pair]      = x0 * cv - x1 * sv;
    base[pair + 32] = x1 * cv + x0 * sv;
}

// ============================================================================
// Flash attention, fp32, causal (unchanged — proven correct in R2/R3).
// ============================================================================
__global__ __launch_bounds__(256) void attn_kernel(
    const float* __restrict__ q, const float* __restrict__ k,
    const float* __restrict__ v, float* __restrict__ o)
{
    extern __shared__ float sm[];
    float* Qs = sm;
    float* Ks = sm + 64 * 65;
    float* Vs = sm + 2 * 64 * 65;
    float* Ss = sm + 3 * 64 * 65;

    const int qt  = blockIdx.x;
    const int h   = blockIdx.y;
    const int b   = blockIdx.z;
    const int kvh = h >> 2;
    const int q0  = qt << 6;
    const int tid = threadIdx.x;

    for (int i = tid; i < 1024; i += 256) {
        int r  = i >> 4;
        int d4 = (i & 15) << 2;
        float4 t4 = *(const float4*)(q + (size_t)(b * S_LEN + q0 + r) * HID + h * HDIM + d4);
        float* dst = Qs + r * 65 + d4;
        dst[0] = t4.x; dst[1] = t4.y; dst[2] = t4.z; dst[3] = t4.w;
    }

    const int tr  = (tid >> 4) << 2;
    const int tc  = (tid & 15) << 2;
    const int row = tid >> 2;
    const int c0  = (tid & 3) << 4;

    float oacc[16];
#pragma unroll
    for (int i = 0; i < 16; ++i) oacc[i] = 0.f;
    float m_i = -INFINITY, l_i = 0.f;

    __syncthreads();

    for (int kt = 0; kt <= qt; ++kt) {
        const int k0 = kt << 6;

        for (int i = tid; i < 1024; i += 256) {
            int r  = i >> 4;
            int d4 = (i & 15) << 2;
            size_t g = (size_t)(b * S_LEN + k0 + r) * KVDIM + kvh * HDIM + d4;
            float4 k4 = *(const float4*)(k + g);
            float4 v4 = *(const float4*)(v + g);
            float* kd = Ks + r * 65 + d4;
            kd[0] = k4.x; kd[1] = k4.y; kd[2] = k4.z; kd[3] = k4.w;
            float* vd = Vs + r * 65 + d4;
            vd[0] = v4.x; vd[1] = v4.y; vd[2] = v4.z; vd[3] = v4.w;
        }
        __syncthreads();

        float sc[4][4];
#pragma unroll
        for (int i = 0; i < 4; ++i)
#pragma unroll
            for (int j = 0; j < 4; ++j) sc[i][j] = 0.f;

#pragma unroll 8
        for (int d = 0; d < 64; ++d) {
            float qa[4], kb4[4];
#pragma unroll
            for (int i = 0; i < 4; ++i) qa[i]  = Qs[(tr + i) * 65 + d];
#pragma unroll
            for (int j = 0; j < 4; ++j) kb4[j] = Ks[(tc + j) * 65 + d];
#pragma unroll
            for (int i = 0; i < 4; ++i)
#pragma unroll
                for (int j = 0; j < 4; ++j)
                    sc[i][j] += qa[i] * kb4[j];
        }

#pragma unroll
        for (int i = 0; i < 4; ++i)
#pragma unroll
            for (int j = 0; j < 4; ++j) {
                int qg = q0 + tr + i;
                int kg = k0 + tc + j;
                float sval = sc[i][j] * 0.125f;
                if (kg > qg) sval = -INFINITY;
                Ss[(tr + i) * 65 + tc + j] = sval;
            }
        __syncwarp();

        float* srow = Ss + row * 65;
        float tmax = -INFINITY;
#pragma unroll
        for (int c = 0; c < 16; ++c) tmax = fmaxf(tmax, srow[c0 + c]);
        tmax = fmaxf(tmax, __shfl_xor_sync(0xffffffffu, tmax, 1));
        tmax = fmaxf(tmax, __shfl_xor_sync(0xffffffffu, tmax, 2));

        float m_new = fmaxf(m_i, tmax);
        float corr  = __expf(m_i - m_new);
        float lsum  = 0.f;
#pragma unroll
        for (int c = 0; c < 16; ++c) {
            float p = __expf(srow[c0 + c] - m_new);
            srow[c0 + c] = p;
            lsum += p;
        }
        lsum += __shfl_xor_sync(0xffffffffu, lsum, 1);
        lsum += __shfl_xor_sync(0xffffffffu, lsum, 2);
        l_i = l_i * corr + lsum;
        m_i = m_new;
#pragma unroll
        for (int i = 0; i < 16; ++i) oacc[i] *= corr;
        __syncwarp();

#pragma unroll 4
        for (int c = 0; c < 64; ++c) {
            float p = srow[c];
            const float* vrow = Vs + c * 65 + c0;
#pragma unroll
            for (int dd = 0; dd < 16; ++dd)
                oacc[dd] += p * vrow[dd];
        }
        __syncthreads();
    }

    float invl = 1.f / l_i;
    float* ob = o + (size_t)(b * S_LEN + q0 + row) * HID + h * HDIM + c0;
#pragma unroll
    for (int dd = 0; dd < 16; ++dd) ob[dd] = oacc[dd] * invl;
}

// ============================================================================
// kernel_launch
// ============================================================================
extern "C" void kernel_launch(void* const* d_in, const int* in_sizes, int n_in,
                              void* d_out, int out_size)
{
    (void)in_sizes; (void)n_in; (void)out_size;
    const float* x  = (const float*)d_in[0];
    const float* Wq = (const float*)d_in[1];
    const float* Wk = (const float*)d_in[2];
    const float* Wv = (const float*)d_in[3];
    const float* Wo = (const float*)d_in[4];
    float* out = (float*)d_out;

    float *qb, *kb, *vb, *ab, *rc, *rs;
    cudaGetSymbolAddress((void**)&qb, g_q);
    cudaGetSymbolAddress((void**)&kb, g_k);
    cudaGetSymbolAddress((void**)&vb, g_v);
    cudaGetSymbolAddress((void**)&ab, g_attn);
    cudaGetSymbolAddress((void**)&rc, g_rc);
    cudaGetSymbolAddress((void**)&rs, g_rs);

    __nv_bfloat16 *xh, *xl, *wqh, *wql, *wkh, *wkl, *wvh, *wvl, *woh, *wol, *ah, *al;
    cudaGetSymbolAddress((void**)&xh,  g_xh);
    cudaGetSymbolAddress((void**)&xl,  g_xl);
    cudaGetSymbolAddress((void**)&wqh, g_wqh);
    cudaGetSymbolAddress((void**)&wql, g_wql);
    cudaGetSymbolAddress((void**)&wkh, g_wkh);
    cudaGetSymbolAddress((void**)&wkl, g_wkl);
    cudaGetSymbolAddress((void**)&wvh, g_wvh);
    cudaGetSymbolAddress((void**)&wvl, g_wvl);
    cudaGetSymbolAddress((void**)&woh, g_woh);
    cudaGetSymbolAddress((void**)&wol, g_wol);
    cudaGetSymbolAddress((void**)&ah,  g_ah);
    cudaGetSymbolAddress((void**)&al,  g_al);

    cudaFuncSetAttribute(gemm_mma, cudaFuncAttributeMaxDynamicSharedMemorySize, GEMM_SMEM);

    const int M = MROWS;

    // split fp32 -> bf16 hi/lo
    const int nx = M * HID, nwq = HID * HID, nwk = KVDIM * HID;
    split_bf16<<<(nx  + 255) / 256, 256>>>(x,  xh,  xl,  nx);
    split_bf16<<<(nwq + 255) / 256, 256>>>(Wq, wqh, wql, nwq);
    split_bf16<<<(nwk + 255) / 256, 256>>>(Wk, wkh, wkl, nwk);
    split_bf16<<<(nwk + 255) / 256, 256>>>(Wv, wvh, wvl, nwk);
    split_bf16<<<(nwq + 255) / 256, 256>>>(Wo, woh, wol, nwq);

    // QKV projections (mma.sync bf16 hi/lo)
    gemm_mma<<<dim3(HID / BN,   M / BM), 256, GEMM_SMEM>>>(xh, xl, wqh, wql, qb, M, HID,   HID);
    gemm_mma<<<dim3(KVDIM / BN, M / BM), 256, GEMM_SMEM>>>(xh, xl, wkh, wkl, kb, M, KVDIM, HID);
    gemm_mma<<<dim3(KVDIM / BN, M / BM), 256, GEMM_SMEM>>>(xh, xl, wvh, wvl, vb, M, KVDIM, HID);

    // RoPE
    rope_table<<<(S_LEN * 32 + 255) / 256, 256>>>(rc, rs);
    const int rope_tot = M * (NHEADS + KVHEADS) * 32;
    rope_apply<<<(rope_tot + 255) / 256, 256>>>(qb, kb, rc, rs);

    // causal GQA flash attention (fp32)
    static const int ATTN_SMEM = 4 * 64 * 65 * (int)sizeof(float);
    cudaFuncSetAttribute(attn_kernel, cudaFuncAttributeMaxDynamicSharedMemorySize, ATTN_SMEM);
    attn_kernel<<<dim3(S_LEN / 64, NHEADS, BATCH), 256, ATTN_SMEM>>>(qb, kb, vb, ab);

    // output projection
    split_bf16<<<(nx + 255) / 256, 256>>>(ab, ah, al, nx);
    gemm_mma<<<dim3(HID / BN, M / BM), 256, GEMM_SMEM>>>(ah, al, woh, wol, out, M, HID, HID);
}

// round 6
// speedup vs baseline: 3.3613x; 2.6481x over previous
#include <cuda_runtime.h>
#include <cuda_bf16.h>
#include <math.h>
#include <stdint.h>

#define S_LEN   2048
#define BATCH   2
#define HID     2048
#define NHEADS  32
#define KVHEADS 8
#define HDIM    64
#define MROWS   (BATCH * S_LEN)     // 4096
#define KVDIM   (KVHEADS * HDIM)    // 512

// ---------------- scratch (static device globals; no allocations) ----------
__device__ float g_q[(size_t)MROWS * HID];
__device__ float g_k[(size_t)MROWS * KVDIM];
__device__ float g_v[(size_t)MROWS * KVDIM];

__device__ __nv_bfloat16 g_xh[(size_t)MROWS * HID];
__device__ __nv_bfloat16 g_xl[(size_t)MROWS * HID];
__device__ __nv_bfloat16 g_wqh[(size_t)HID * HID];
__device__ __nv_bfloat16 g_wql[(size_t)HID * HID];
__device__ __nv_bfloat16 g_wkh[(size_t)KVDIM * HID];
__device__ __nv_bfloat16 g_wkl[(size_t)KVDIM * HID];
__device__ __nv_bfloat16 g_wvh[(size_t)KVDIM * HID];
__device__ __nv_bfloat16 g_wvl[(size_t)KVDIM * HID];
__device__ __nv_bfloat16 g_woh[(size_t)HID * HID];
__device__ __nv_bfloat16 g_wol[(size_t)HID * HID];
__device__ __nv_bfloat16 g_ah[(size_t)MROWS * HID];
__device__ __nv_bfloat16 g_al[(size_t)MROWS * HID];

// rotated Q/K in bf16 hi/lo (attention inputs)
__device__ __nv_bfloat16 g_qh[(size_t)MROWS * HID];
__device__ __nv_bfloat16 g_ql[(size_t)MROWS * HID];
__device__ __nv_bfloat16 g_kh[(size_t)MROWS * KVDIM];
__device__ __nv_bfloat16 g_kl[(size_t)MROWS * KVDIM];
__device__ __nv_bfloat16 g_vh[(size_t)MROWS * KVDIM];
__device__ __nv_bfloat16 g_vl[(size_t)MROWS * KVDIM];

__device__ float g_rc[S_LEN * 32];
__device__ float g_rs[S_LEN * 32];

// ============================================================================
// PTX helpers (plain sm_103-safe)
// ============================================================================
__device__ __forceinline__ uint32_t smem_to_u32(const void* p) {
    uint32_t a;
    asm("{ .reg .u64 t; cvta.to.shared.u64 t, %1; cvt.u32.u64 %0, t; }"
        : "=r"(a) : "l"(p));
    return a;
}

#define CP_ASYNC16(smem, gmem) \
    asm volatile("cp.async.cg.shared.global [%0], [%1], 16;" \
                 :: "r"(smem), "l"(gmem) : "memory")
#define CP_COMMIT() asm volatile("cp.async.commit_group;" ::: "memory")
#define CP_WAIT(n)  asm volatile("cp.async.wait_group %0;" :: "n"(n) : "memory")

__device__ __forceinline__ void ldsm_x4(uint32_t* r, uint32_t addr) {
    asm volatile("ldmatrix.sync.aligned.m8n8.x4.shared.b16 {%0,%1,%2,%3}, [%4];"
        : "=r"(r[0]), "=r"(r[1]), "=r"(r[2]), "=r"(r[3]) : "r"(addr));
}
__device__ __forceinline__ void ldsm_x2(uint32_t* r, uint32_t addr) {
    asm volatile("ldmatrix.sync.aligned.m8n8.x2.shared.b16 {%0,%1}, [%2];"
        : "=r"(r[0]), "=r"(r[1]) : "r"(addr));
}
__device__ __forceinline__ void ldsm_x2_trans(uint32_t* r, uint32_t addr) {
    asm volatile("ldmatrix.sync.aligned.m8n8.x2.trans.shared.b16 {%0,%1}, [%2];"
        : "=r"(r[0]), "=r"(r[1]) : "r"(addr));
}

__device__ __forceinline__ void mma16816(float* d, const uint32_t* a, const uint32_t* b) {
    asm volatile(
        "mma.sync.aligned.m16n8k16.row.col.f32.bf16.bf16.f32 "
        "{%0,%1,%2,%3}, {%4,%5,%6,%7}, {%8,%9}, {%0,%1,%2,%3};"
        : "+f"(d[0]), "+f"(d[1]), "+f"(d[2]), "+f"(d[3])
        : "r"(a[0]), "r"(a[1]), "r"(a[2]), "r"(a[3]), "r"(b[0]), "r"(b[1]));
}

// pack two floats into bf16x2 (lo=a, hi=b) plus residual bf16x2
__device__ __forceinline__ void pack_hilo(float a, float b, uint32_t& hi, uint32_t& lo) {
    __nv_bfloat16 ha = __float2bfloat16(a);
    __nv_bfloat16 hb = __float2bfloat16(b);
    __nv_bfloat162 H; H.x = ha; H.y = hb;
    hi = *reinterpret_cast<uint32_t*>(&H);
    __nv_bfloat162 L;
    L.x = __float2bfloat16(a - __bfloat162float(ha));
    L.y = __float2bfloat16(b - __bfloat162float(hb));
    lo = *reinterpret_cast<uint32_t*>(&L);
}

// ============================================================================
// fp32 -> bf16 hi/lo split
// ============================================================================
__global__ void split_bf16(const float* __restrict__ in,
                           __nv_bfloat16* __restrict__ hi,
                           __nv_bfloat16* __restrict__ lo, int n)
{
    int i = blockIdx.x * blockDim.x + threadIdx.x;
    if (i >= n) return;
    float v = in[i];
    __nv_bfloat16 h = __float2bfloat16(v);
    hi[i] = h;
    lo[i] = __float2bfloat16(v - __bfloat162float(h));
}

// ============================================================================
// bf16 hi/lo split GEMM via mma.sync (unchanged from R4 — proven)
// ============================================================================
#define BM 128
#define BN 128
#define BK 32
#define ROWB   80
#define ASZ    (128 * ROWB)
#define STAGE  (4 * ASZ)
#define GEMM_SMEM (2 * STAGE)

__global__ __launch_bounds__(256, 1) void gemm_mma(
    const __nv_bfloat16* __restrict__ Ah, const __nv_bfloat16* __restrict__ Al,
    const __nv_bfloat16* __restrict__ Bh, const __nv_bfloat16* __restrict__ Bl,
    float* __restrict__ C, int M, int N, int K)
{
    extern __shared__ char smem[];
    const uint32_t sbase = smem_to_u32(smem);

    const int tid  = threadIdx.x;
    const int wid  = tid >> 5;
    const int lane = tid & 31;
    const int wm   = wid >> 2;
    const int wn   = wid & 3;
    const int bm   = blockIdx.y * BM;
    const int bn   = blockIdx.x * BN;

    const __nv_bfloat16* gAh = Ah + (size_t)bm * K;
    const __nv_bfloat16* gAl = Al + (size_t)bm * K;
    const __nv_bfloat16* gBh = Bh + (size_t)bn * K;
    const __nv_bfloat16* gBl = Bl + (size_t)bn * K;

    const int NC = K / BK;

    const int lr  = tid >> 2;
    const int lsg = tid & 3;
    auto issue = [&](int kc, int buf) {
        const uint32_t sb = sbase + buf * STAGE;
        const size_t kofs = (size_t)kc * BK + lsg * 8;
#pragma unroll
        for (int t = 0; t < 2; ++t) {
            int r = lr + t * 64;
            uint32_t so = (uint32_t)(r * ROWB + lsg * 16);
            size_t g = (size_t)r * K + kofs;
            CP_ASYNC16(sb + so,           gAh + g);
            CP_ASYNC16(sb + ASZ + so,     gAl + g);
            CP_ASYNC16(sb + 2 * ASZ + so, gBh + g);
            CP_ASYNC16(sb + 3 * ASZ + so, gBl + g);
        }
        CP_COMMIT();
    };

    float acc[4][4][4];
#pragma unroll
    for (int i = 0; i < 4; ++i)
#pragma unroll
        for (int j = 0; j < 4; ++j)
#pragma unroll
            for (int c = 0; c < 4; ++c) acc[i][j][c] = 0.f;

    const uint32_t a_row  = (uint32_t)(wm * 64 + (lane & 15));
    const uint32_t a_colb = (uint32_t)((lane >> 4) * 16);
    const uint32_t b_row  = (uint32_t)(wn * 32 + (lane & 7));
    const uint32_t b_colb = (uint32_t)(((lane >> 3) & 1) * 16);

    issue(0, 0);

    for (int kt = 0; kt < NC; ++kt) {
        const int buf = kt & 1;
        if (kt + 1 < NC) { issue(kt + 1, buf ^ 1); CP_WAIT(1); }
        else             { CP_WAIT(0); }
        __syncthreads();

        const uint32_t sAh = sbase + buf * STAGE;
        const uint32_t sAl = sAh + ASZ;
        const uint32_t sBh = sAh + 2 * ASZ;
        const uint32_t sBl = sAh + 3 * ASZ;

#pragma unroll
        for (int ks = 0; ks < 2; ++ks) {
            const uint32_t kofs = ks * 32;

            uint32_t ah[4][4], al[4][4], bb[4][2];
#pragma unroll
            for (int mt = 0; mt < 4; ++mt) {
                uint32_t off = (a_row + mt * 16) * ROWB + a_colb + kofs;
                ldsm_x4(ah[mt], sAh + off);
                ldsm_x4(al[mt], sAl + off);
            }
#pragma unroll
            for (int nt = 0; nt < 4; ++nt) {
                uint32_t off = (b_row + nt * 8) * ROWB + b_colb + kofs;
                ldsm_x2(bb[nt], sBh + off);
            }
#pragma unroll
            for (int mt = 0; mt < 4; ++mt)
#pragma unroll
                for (int nt = 0; nt < 4; ++nt) {
                    mma16816(acc[mt][nt], ah[mt], bb[nt]);
                    mma16816(acc[mt][nt], al[mt], bb[nt]);
                }
#pragma unroll
            for (int nt = 0; nt < 4; ++nt) {
                uint32_t off = (b_row + nt * 8) * ROWB + b_colb + kofs;
                ldsm_x2(bb[nt], sBl + off);
            }
#pragma unroll
            for (int mt = 0; mt < 4; ++mt)
#pragma unroll
                for (int nt = 0; nt < 4; ++nt)
                    mma16816(acc[mt][nt], ah[mt], bb[nt]);
        }
        __syncthreads();
    }

    const int er = lane >> 2;
    const int ec = (lane & 3) * 2;
#pragma unroll
    for (int mt = 0; mt < 4; ++mt) {
        const int row0 = bm + wm * 64 + mt * 16 + er;
#pragma unroll
        for (int nt = 0; nt < 4; ++nt) {
            const int col = bn + wn * 32 + nt * 8 + ec;
            float2 v0 = {acc[mt][nt][0], acc[mt][nt][1]};
            float2 v1 = {acc[mt][nt][2], acc[mt][nt][3]};
            *(float2*)(C + (size_t)row0 * N + col)       = v0;
            *(float2*)(C + (size_t)(row0 + 8) * N + col) = v1;
        }
    }
}

// ============================================================================
// RoPE tables + fused rope+split (fp32 q/k -> rotated bf16 hi/lo)
// ============================================================================
__global__ void rope_table(float* __restrict__ ct, float* __restrict__ st)
{
    int t = blockIdx.x * blockDim.x + threadIdx.x;
    if (t >= S_LEN * 32) return;
    int pos  = t >> 5;
    int pair = t & 31;
    float inv = (float)exp(-(double)pair * (9.210340371976184 / 32.0));
    float a = (float)pos * inv;
    float s, c;
    sincosf(a, &s, &c);
    ct[t] = c;
    st[t] = s;
}

__global__ void rope_split(const float* __restrict__ qs, const float* __restrict__ ks,
                           const float* __restrict__ ct, const float* __restrict__ st,
                           __nv_bfloat16* __restrict__ qh, __nv_bfloat16* __restrict__ ql,
                           __nv_bfloat16* __restrict__ kh, __nv_bfloat16* __restrict__ kl)
{
    const int TOT = MROWS * (NHEADS + KVHEADS) * 32;
    int t = blockIdx.x * blockDim.x + threadIdx.x;
    if (t >= TOT) return;

    int pair = t & 31;
    int rest = t >> 5;
    int head = rest % (NHEADS + KVHEADS);
    int row  = rest / (NHEADS + KVHEADS);
    int pos  = row & (S_LEN - 1);

    float cv = ct[pos * 32 + pair];
    float sv = st[pos * 32 + pair];

    const float* src;
    __nv_bfloat16 *H, *L;
    size_t base;
    if (head < NHEADS) {
        base = (size_t)row * HID + head * HDIM;
        src = qs + base; H = qh; L = ql;
    } else {
        base = (size_t)row * KVDIM + (head - NHEADS) * HDIM;
        src = ks + base; H = kh; L = kl;
    }

    float x0 = src[pair];
    float x1 = src[pair + 32];
    float y0 = x0 * cv - x1 * sv;
    float y1 = x1 * cv + x0 * sv;

    __nv_bfloat16 h0 = __float2bfloat16(y0);
    __nv_bfloat16 h1 = __float2bfloat16(y1);
    H[base + pair]      = h0;
    H[base + pair + 32] = h1;
    L[base + pair]      = __float2bfloat16(y0 - __bfloat162float(h0));
    L[base + pair + 32] = __float2bfloat16(y1 - __bfloat162float(h1));
}

// ============================================================================
// Tensor-core flash attention (bf16 hi/lo, fp32 accum, causal)
// CTA = (qtile 64 rows, head, batch); 4 warps x 16 rows.
// K/V 64x64 tiles double-buffered via cp.async; Q fragments in registers.
// Output written directly as bf16 hi/lo (feeds the Wo GEMM).
// ============================================================================
#define AT_ROWB 144                    // 64 bf16 + 8 pad, bytes per smem row
#define AT_TILE (64 * AT_ROWB)         // 9216 B
#define ATTN_SMEM (10 * AT_TILE)       // Qh,Ql + 2 bufs x (Kh,Kl,Vh,Vl)

__global__ __launch_bounds__(128) void attn_mma(
    const __nv_bfloat16* __restrict__ qh, const __nv_bfloat16* __restrict__ ql,
    const __nv_bfloat16* __restrict__ kh, const __nv_bfloat16* __restrict__ kl,
    const __nv_bfloat16* __restrict__ vh, const __nv_bfloat16* __restrict__ vl,
    __nv_bfloat16* __restrict__ oh, __nv_bfloat16* __restrict__ ol)
{
    extern __shared__ char smem[];
    const uint32_t sbase = smem_to_u32(smem);

    const int qt  = blockIdx.x;
    const int h   = blockIdx.y;
    const int b   = blockIdx.z;
    const int kvh = h >> 2;
    const int q0  = qt << 6;
    const int tid = threadIdx.x;
    const int warp = tid >> 5;
    const int lane = tid & 31;

    const uint32_t sQh = sbase;
    const uint32_t sQl = sbase + AT_TILE;
    // KV tile offsets: tile(buf, t) t in {Kh=0, Kl=1, Vh=2, Vl=3}
    auto kvtile = [&](int buf, int t) -> uint32_t {
        return sbase + 2 * AT_TILE + (buf * 4 + t) * AT_TILE;
    };

    // ---- loaders (128 threads: thread -> row tid/2, 4x16B segments) ----
    const int lrow = tid >> 1;
    const int lsg  = (tid & 1) * 4;

    // Q: group 0
    {
        const size_t grow = (size_t)(b * S_LEN + q0 + lrow) * HID + h * HDIM;
#pragma unroll
        for (int i = 0; i < 4; ++i) {
            int seg = lsg + i;
            uint32_t so = (uint32_t)(lrow * AT_ROWB + seg * 16);
            CP_ASYNC16(sQh + so, qh + grow + seg * 8);
            CP_ASYNC16(sQl + so, ql + grow + seg * 8);
        }
        CP_COMMIT();
    }

    auto issue_kv = [&](int kt, int buf) {
        const size_t grow = (size_t)(b * S_LEN + kt * 64 + lrow) * KVDIM + kvh * HDIM;
        const uint32_t t0 = kvtile(buf, 0), t1 = kvtile(buf, 1);
        const uint32_t t2 = kvtile(buf, 2), t3 = kvtile(buf, 3);
#pragma unroll
        for (int i = 0; i < 4; ++i) {
            int seg = lsg + i;
            uint32_t so = (uint32_t)(lrow * AT_ROWB + seg * 16);
            CP_ASYNC16(t0 + so, kh + grow + seg * 8);
            CP_ASYNC16(t1 + so, kl + grow + seg * 8);
            CP_ASYNC16(t2 + so, vh + grow + seg * 8);
            CP_ASYNC16(t3 + so, vl + grow + seg * 8);
        }
        CP_COMMIT();
    };

    issue_kv(0, 0);

    // fragment indices
    const uint32_t a_row  = (uint32_t)(warp * 16 + (lane & 15));
    const uint32_t a_colb = (uint32_t)((lane >> 4) * 16);
    const uint32_t kb_row = (uint32_t)(lane & 7);
    const uint32_t kb_sel = (uint32_t)(((lane >> 3) & 1) * 16);
    const uint32_t v_row  = (uint32_t)(lane & 15);

    const int er = lane >> 2;
    const int ec = (lane & 3) * 2;
    const int qg0 = q0 + warp * 16 + er;   // sequence-local q row
    const int qg1 = qg0 + 8;

    uint32_t qhf[4][4], qlf[4][4];

    float o[8][4];
#pragma unroll
    for (int i = 0; i < 8; ++i)
#pragma unroll
        for (int c = 0; c < 4; ++c) o[i][c] = 0.f;
    float m0 = -INFINITY, m1 = -INFINITY, l0 = 0.f, l1 = 0.f;

    for (int kt = 0; kt <= qt; ++kt) {
        const int buf = kt & 1;
        if (kt + 1 <= qt) { issue_kv(kt + 1, buf ^ 1); CP_WAIT(1); }
        else              { CP_WAIT(0); }
        __syncthreads();

        if (kt == 0) {   // Q fragments (group 0 complete by now)
#pragma unroll
            for (int ks = 0; ks < 4; ++ks) {
                uint32_t off = a_row * AT_ROWB + a_colb + ks * 32;
                ldsm_x4(qhf[ks], sQh + off);
                ldsm_x4(qlf[ks], sQl + off);
            }
        }

        // ---- S = Q K^T (hi/lo 3-term) ----
        float s[8][4];
#pragma unroll
        for (int nt = 0; nt < 8; ++nt)
#pragma unroll
            for (int c = 0; c < 4; ++c) s[nt][c] = 0.f;

        const uint32_t sKh = kvtile(buf, 0), sKl = kvtile(buf, 1);
#pragma unroll
        for (int nt = 0; nt < 8; ++nt) {
#pragma unroll
            for (int ks = 0; ks < 4; ++ks) {
                uint32_t off = (nt * 8 + kb_row) * AT_ROWB + kb_sel + ks * 32;
                uint32_t kfh[2], kfl[2];
                ldsm_x2(kfh, sKh + off);
                ldsm_x2(kfl, sKl + off);
                mma16816(s[nt], qhf[ks], kfh);
                mma16816(s[nt], qhf[ks], kfl);
                mma16816(s[nt], qlf[ks], kfh);
            }
        }

        // ---- scale + causal mask (diagonal tile only) ----
        const int k0 = kt << 6;
#pragma unroll
        for (int nt = 0; nt < 8; ++nt)
#pragma unroll
            for (int c = 0; c < 4; ++c) s[nt][c] *= 0.125f;

        if (kt == qt) {
#pragma unroll
            for (int nt = 0; nt < 8; ++nt) {
                int kg = k0 + nt * 8 + ec;
                if (kg     > qg0) s[nt][0] = -INFINITY;
                if (kg + 1 > qg0) s[nt][1] = -INFINITY;
                if (kg     > qg1) s[nt][2] = -INFINITY;
                if (kg + 1 > qg1) s[nt][3] = -INFINITY;
            }
        }

        // ---- online softmax (registers, quad reductions) ----
        float mx0 = -INFINITY, mx1 = -INFINITY;
#pragma unroll
        for (int nt = 0; nt < 8; ++nt) {
            mx0 = fmaxf(mx0, fmaxf(s[nt][0], s[nt][1]));
            mx1 = fmaxf(mx1, fmaxf(s[nt][2], s[nt][3]));
        }
        mx0 = fmaxf(mx0, __shfl_xor_sync(0xffffffffu, mx0, 1));
        mx0 = fmaxf(mx0, __shfl_xor_sync(0xffffffffu, mx0, 2));
        mx1 = fmaxf(mx1, __shfl_xor_sync(0xffffffffu, mx1, 1));
        mx1 = fmaxf(mx1, __shfl_xor_sync(0xffffffffu, mx1, 2));

        float mn0 = fmaxf(m0, mx0), mn1 = fmaxf(m1, mx1);
        float cr0 = __expf(m0 - mn0), cr1 = __expf(m1 - mn1);

        float ls0 = 0.f, ls1 = 0.f;
#pragma unroll
        for (int nt = 0; nt < 8; ++nt) {
            s[nt][0] = __expf(s[nt][0] - mn0);
            s[nt][1] = __expf(s[nt][1] - mn0);
            s[nt][2] = __expf(s[nt][2] - mn1);
            s[nt][3] = __expf(s[nt][3] - mn1);
            ls0 += s[nt][0] + s[nt][1];
            ls1 += s[nt][2] + s[nt][3];
        }
        ls0 += __shfl_xor_sync(0xffffffffu, ls0, 1);
        ls0 += __shfl_xor_sync(0xffffffffu, ls0, 2);
        ls1 += __shfl_xor_sync(0xffffffffu, ls1, 1);
        ls1 += __shfl_xor_sync(0xffffffffu, ls1, 2);
        l0 = l0 * cr0 + ls0;
        l1 = l1 * cr1 + ls1;
        m0 = mn0; m1 = mn1;

#pragma unroll
        for (int nt = 0; nt < 8; ++nt) {
            o[nt][0] *= cr0; o[nt][1] *= cr0;
            o[nt][2] *= cr1; o[nt][3] *= cr1;
        }

        // ---- pack P into A fragments (hi/lo) ----
        uint32_t ph[4][4], pl[4][4];
#pragma unroll
        for (int ks = 0; ks < 4; ++ks) {
            pack_hilo(s[2 * ks][0],     s[2 * ks][1],     ph[ks][0], pl[ks][0]);
            pack_hilo(s[2 * ks][2],     s[2 * ks][3],     ph[ks][1], pl[ks][1]);
            pack_hilo(s[2 * ks + 1][0], s[2 * ks + 1][1], ph[ks][2], pl[ks][2]);
            pack_hilo(s[2 * ks + 1][2], s[2 * ks + 1][3], ph[ks][3], pl[ks][3]);
        }

        // ---- O += P V (hi/lo 3-term, V via trans ldmatrix) ----
        const uint32_t sVh = kvtile(buf, 2), sVl = kvtile(buf, 3);
#pragma unroll
        for (int nt = 0; nt < 8; ++nt) {
#pragma unroll
            for (int ks = 0; ks < 4; ++ks) {
                uint32_t off = (ks * 16 + v_row) * AT_ROWB + nt * 16;
                uint32_t vfh[2], vfl[2];
                ldsm_x2_trans(vfh, sVh + off);
                ldsm_x2_trans(vfl, sVl + off);
                mma16816(o[nt], ph[ks], vfh);
                mma16816(o[nt], ph[ks], vfl);
                mma16816(o[nt], pl[ks], vfh);
            }
        }
        __syncthreads();   // before next iteration's issue overwrites this buf
    }

    // ---- epilogue: O/l -> bf16 hi/lo output ----
    const float il0 = 1.f / l0, il1 = 1.f / l1;
    const size_t row0 = (size_t)(b * S_LEN + qg0);
    const size_t row1 = (size_t)(b * S_LEN + qg1);
#pragma unroll
    for (int nt = 0; nt < 8; ++nt) {
        const int col = h * HDIM + nt * 8 + ec;
        uint32_t hi, lo;
        pack_hilo(o[nt][0] * il0, o[nt][1] * il0, hi, lo);
        *(uint32_t*)(oh + row0 * HID + col) = hi;
        *(uint32_t*)(ol + row0 * HID + col) = lo;
        pack_hilo(o[nt][2] * il1, o[nt][3] * il1, hi, lo);
        *(uint32_t*)(oh + row1 * HID + col) = hi;
        *(uint32_t*)(ol + row1 * HID + col) = lo;
    }
}

// ============================================================================
// kernel_launch
// ============================================================================
extern "C" void kernel_launch(void* const* d_in, const int* in_sizes, int n_in,
                              void* d_out, int out_size)
{
    (void)in_sizes; (void)n_in; (void)out_size;
    const float* x  = (const float*)d_in[0];
    const float* Wq = (const float*)d_in[1];
    const float* Wk = (const float*)d_in[2];
    const float* Wv = (const float*)d_in[3];
    const float* Wo = (const float*)d_in[4];
    float* out = (float*)d_out;

    float *qb, *kb, *vb, *rc, *rs;
    cudaGetSymbolAddress((void**)&qb, g_q);
    cudaGetSymbolAddress((void**)&kb, g_k);
    cudaGetSymbolAddress((void**)&vb, g_v);
    cudaGetSymbolAddress((void**)&rc, g_rc);
    cudaGetSymbolAddress((void**)&rs, g_rs);

    __nv_bfloat16 *xh, *xl, *wqh, *wql, *wkh, *wkl, *wvh, *wvl, *woh, *wol, *ah, *al;
    __nv_bfloat16 *qhb, *qlb, *khb, *klb, *vhb, *vlb;
    cudaGetSymbolAddress((void**)&xh,  g_xh);
    cudaGetSymbolAddress((void**)&xl,  g_xl);
    cudaGetSymbolAddress((void**)&wqh, g_wqh);
    cudaGetSymbolAddress((void**)&wql, g_wql);
    cudaGetSymbolAddress((void**)&wkh, g_wkh);
    cudaGetSymbolAddress((void**)&wkl, g_wkl);
    cudaGetSymbolAddress((void**)&wvh, g_wvh);
    cudaGetSymbolAddress((void**)&wvl, g_wvl);
    cudaGetSymbolAddress((void**)&woh, g_woh);
    cudaGetSymbolAddress((void**)&wol, g_wol);
    cudaGetSymbolAddress((void**)&ah,  g_ah);
    cudaGetSymbolAddress((void**)&al,  g_al);
    cudaGetSymbolAddress((void**)&qhb, g_qh);
    cudaGetSymbolAddress((void**)&qlb, g_ql);
    cudaGetSymbolAddress((void**)&khb, g_kh);
    cudaGetSymbolAddress((void**)&klb, g_kl);
    cudaGetSymbolAddress((void**)&vhb, g_vh);
    cudaGetSymbolAddress((void**)&vlb, g_vl);

    cudaFuncSetAttribute(gemm_mma, cudaFuncAttributeMaxDynamicSharedMemorySize, GEMM_SMEM);
    cudaFuncSetAttribute(attn_mma, cudaFuncAttributeMaxDynamicSharedMemorySize, ATTN_SMEM);

    const int M = MROWS;

    // split fp32 -> bf16 hi/lo
    const int nx = M * HID, nwq = HID * HID, nwk = KVDIM * HID;
    split_bf16<<<(nx  + 255) / 256, 256>>>(x,  xh,  xl,  nx);
    split_bf16<<<(nwq + 255) / 256, 256>>>(Wq, wqh, wql, nwq);
    split_bf16<<<(nwk + 255) / 256, 256>>>(Wk, wkh, wkl, nwk);
    split_bf16<<<(nwk + 255) / 256, 256>>>(Wv, wvh, wvl, nwk);
    split_bf16<<<(nwq + 255) / 256, 256>>>(Wo, woh, wol, nwq);

    // QKV projections
    gemm_mma<<<dim3(HID / BN,   M / BM), 256, GEMM_SMEM>>>(xh, xl, wqh, wql, qb, M, HID,   HID);
    gemm_mma<<<dim3(KVDIM / BN, M / BM), 256, GEMM_SMEM>>>(xh, xl, wkh, wkl, kb, M, KVDIM, HID);
    gemm_mma<<<dim3(KVDIM / BN, M / BM), 256, GEMM_SMEM>>>(xh, xl, wvh, wvl, vb, M, KVDIM, HID);

    // RoPE + bf16 hi/lo conversion for attention
    rope_table<<<(S_LEN * 32 + 255) / 256, 256>>>(rc, rs);
    const int rope_tot = M * (NHEADS + KVHEADS) * 32;
    rope_split<<<(rope_tot + 255) / 256, 256>>>(qb, kb, rc, rs, qhb, qlb, khb, klb);
    const int nv = M * KVDIM;
    split_bf16<<<(nv + 255) / 256, 256>>>(vb, vhb, vlb, nv);

    // tensor-core causal flash attention -> bf16 hi/lo output
    attn_mma<<<dim3(S_LEN / 64, NHEADS, BATCH), 128, ATTN_SMEM>>>(
        qhb, qlb, khb, klb, vhb, vlb, ah, al);

    // output projection
    gemm_mma<<<dim3(HID / BN, M / BM), 256, GEMM_SMEM>>>(ah, al, woh, wol, out, M, HID, HID);
}

// round 7
// speedup vs baseline: 3.6659x; 1.0906x over previous
#include <cuda_runtime.h>
#include <cuda_bf16.h>
#include <math.h>
#include <stdint.h>

#define S_LEN   2048
#define BATCH   2
#define HID     2048
#define NHEADS  32
#define KVHEADS 8
#define HDIM    64
#define MROWS   (BATCH * S_LEN)     // 4096
#define KVDIM   (KVHEADS * HDIM)    // 512
#define QKVN    (HID + 2 * KVDIM)   // 3072

// ---------------- scratch (static device globals; no allocations) ----------
__device__ float g_qkv[(size_t)MROWS * QKVN];          // fused QKV output (fp32)

__device__ __nv_bfloat16 g_xh [(size_t)MROWS * HID];
__device__ __nv_bfloat16 g_xl [(size_t)MROWS * HID];
__device__ __nv_bfloat16 g_w3h[(size_t)QKVN * HID];    // packed Wq|Wk|Wv hi
__device__ __nv_bfloat16 g_w3l[(size_t)QKVN * HID];
__device__ __nv_bfloat16 g_woh[(size_t)HID * HID];
__device__ __nv_bfloat16 g_wol[(size_t)HID * HID];
__device__ __nv_bfloat16 g_ah [(size_t)MROWS * HID];
__device__ __nv_bfloat16 g_al [(size_t)MROWS * HID];

__device__ __nv_bfloat16 g_qh[(size_t)MROWS * HID];
__device__ __nv_bfloat16 g_ql[(size_t)MROWS * HID];
__device__ __nv_bfloat16 g_kh[(size_t)MROWS * KVDIM];
__device__ __nv_bfloat16 g_kl[(size_t)MROWS * KVDIM];
__device__ __nv_bfloat16 g_vh[(size_t)MROWS * KVDIM];
__device__ __nv_bfloat16 g_vl[(size_t)MROWS * KVDIM];

__device__ float g_rc[S_LEN * 32];
__device__ float g_rs[S_LEN * 32];

// ============================================================================
// PTX helpers (plain sm_103-safe)
// ============================================================================
__device__ __forceinline__ uint32_t smem_to_u32(const void* p) {
    uint32_t a;
    asm("{ .reg .u64 t; cvta.to.shared.u64 t, %1; cvt.u32.u64 %0, t; }"
        : "=r"(a) : "l"(p));
    return a;
}

#define CP_ASYNC16(smem, gmem) \
    asm volatile("cp.async.cg.shared.global [%0], [%1], 16;" \
                 :: "r"(smem), "l"(gmem) : "memory")
#define CP_COMMIT() asm volatile("cp.async.commit_group;" ::: "memory")
#define CP_WAIT(n)  asm volatile("cp.async.wait_group %0;" :: "n"(n) : "memory")

__device__ __forceinline__ void ldsm_x4(uint32_t* r, uint32_t addr) {
    asm volatile("ldmatrix.sync.aligned.m8n8.x4.shared.b16 {%0,%1,%2,%3}, [%4];"
        : "=r"(r[0]), "=r"(r[1]), "=r"(r[2]), "=r"(r[3]) : "r"(addr));
}
__device__ __forceinline__ void ldsm_x2(uint32_t* r, uint32_t addr) {
    asm volatile("ldmatrix.sync.aligned.m8n8.x2.shared.b16 {%0,%1}, [%2];"
        : "=r"(r[0]), "=r"(r[1]) : "r"(addr));
}
__device__ __forceinline__ void ldsm_x2_trans(uint32_t* r, uint32_t addr) {
    asm volatile("ldmatrix.sync.aligned.m8n8.x2.trans.shared.b16 {%0,%1}, [%2];"
        : "=r"(r[0]), "=r"(r[1]) : "r"(addr));
}

__device__ __forceinline__ void mma16816(float* d, const uint32_t* a, const uint32_t* b) {
    asm volatile(
        "mma.sync.aligned.m16n8k16.row.col.f32.bf16.bf16.f32 "
        "{%0,%1,%2,%3}, {%4,%5,%6,%7}, {%8,%9}, {%0,%1,%2,%3};"
        : "+f"(d[0]), "+f"(d[1]), "+f"(d[2]), "+f"(d[3])
        : "r"(a[0]), "r"(a[1]), "r"(a[2]), "r"(a[3]), "r"(b[0]), "r"(b[1]));
}

__device__ __forceinline__ void pack_hilo(float a, float b, uint32_t& hi, uint32_t& lo) {
    __nv_bfloat16 ha = __float2bfloat16(a);
    __nv_bfloat16 hb = __float2bfloat16(b);
    __nv_bfloat162 H; H.x = ha; H.y = hb;
    hi = *reinterpret_cast<uint32_t*>(&H);
    __nv_bfloat162 L;
    L.x = __float2bfloat16(a - __bfloat162float(ha));
    L.y = __float2bfloat16(b - __bfloat162float(hb));
    lo = *reinterpret_cast<uint32_t*>(&L);
}

// ============================================================================
// fp32 -> bf16 hi/lo split
// ============================================================================
__global__ void split_bf16(const float* __restrict__ in,
                           __nv_bfloat16* __restrict__ hi,
                           __nv_bfloat16* __restrict__ lo, int n)
{
    int i = blockIdx.x * blockDim.x + threadIdx.x;
    if (i >= n) return;
    float v = in[i];
    __nv_bfloat16 h = __float2bfloat16(v);
    hi[i] = h;
    lo[i] = __float2bfloat16(v - __bfloat162float(h));
}

// ============================================================================
// bf16 hi/lo split GEMM via mma.sync (proven R4/R5)
// ============================================================================
#define BM 128
#define BN 128
#define BK 32
#define ROWB   80
#define ASZ    (128 * ROWB)
#define STAGE  (4 * ASZ)
#define GEMM_SMEM (2 * STAGE)

__global__ __launch_bounds__(256, 1) void gemm_mma(
    const __nv_bfloat16* __restrict__ Ah, const __nv_bfloat16* __restrict__ Al,
    const __nv_bfloat16* __restrict__ Bh, const __nv_bfloat16* __restrict__ Bl,
    float* __restrict__ C, int M, int N, int K)
{
    extern __shared__ char smem[];
    const uint32_t sbase = smem_to_u32(smem);

    const int tid  = threadIdx.x;
    const int wid  = tid >> 5;
    const int lane = tid & 31;
    const int wm   = wid >> 2;
    const int wn   = wid & 3;
    const int bm   = blockIdx.y * BM;
    const int bn   = blockIdx.x * BN;

    const __nv_bfloat16* gAh = Ah + (size_t)bm * K;
    const __nv_bfloat16* gAl = Al + (size_t)bm * K;
    const __nv_bfloat16* gBh = Bh + (size_t)bn * K;
    const __nv_bfloat16* gBl = Bl + (size_t)bn * K;

    const int NC = K / BK;

    const int lr  = tid >> 2;
    const int lsg = tid & 3;
    auto issue = [&](int kc, int buf) {
        const uint32_t sb = sbase + buf * STAGE;
        const size_t kofs = (size_t)kc * BK + lsg * 8;
#pragma unroll
        for (int t = 0; t < 2; ++t) {
            int r = lr + t * 64;
            uint32_t so = (uint32_t)(r * ROWB + lsg * 16);
            size_t g = (size_t)r * K + kofs;
            CP_ASYNC16(sb + so,           gAh + g);
            CP_ASYNC16(sb + ASZ + so,     gAl + g);
            CP_ASYNC16(sb + 2 * ASZ + so, gBh + g);
            CP_ASYNC16(sb + 3 * ASZ + so, gBl + g);
        }
        CP_COMMIT();
    };

    float acc[4][4][4];
#pragma unroll
    for (int i = 0; i < 4; ++i)
#pragma unroll
        for (int j = 0; j < 4; ++j)
#pragma unroll
            for (int c = 0; c < 4; ++c) acc[i][j][c] = 0.f;

    const uint32_t a_row  = (uint32_t)(wm * 64 + (lane & 15));
    const uint32_t a_colb = (uint32_t)((lane >> 4) * 16);
    const uint32_t b_row  = (uint32_t)(wn * 32 + (lane & 7));
    const uint32_t b_colb = (uint32_t)(((lane >> 3) & 1) * 16);

    issue(0, 0);

    for (int kt = 0; kt < NC; ++kt) {
        const int buf = kt & 1;
        if (kt + 1 < NC) { issue(kt + 1, buf ^ 1); CP_WAIT(1); }
        else             { CP_WAIT(0); }
        __syncthreads();

        const uint32_t sAh = sbase + buf * STAGE;
        const uint32_t sAl = sAh + ASZ;
        const uint32_t sBh = sAh + 2 * ASZ;
        const uint32_t sBl = sAh + 3 * ASZ;

#pragma unroll
        for (int ks = 0; ks < 2; ++ks) {
            const uint32_t kofs = ks * 32;

            uint32_t ah[4][4], al[4][4], bb[4][2];
#pragma unroll
            for (int mt = 0; mt < 4; ++mt) {
                uint32_t off = (a_row + mt * 16) * ROWB + a_colb + kofs;
                ldsm_x4(ah[mt], sAh + off);
                ldsm_x4(al[mt], sAl + off);
            }
#pragma unroll
            for (int nt = 0; nt < 4; ++nt) {
                uint32_t off = (b_row + nt * 8) * ROWB + b_colb + kofs;
                ldsm_x2(bb[nt], sBh + off);
            }
#pragma unroll
            for (int mt = 0; mt < 4; ++mt)
#pragma unroll
                for (int nt = 0; nt < 4; ++nt) {
                    mma16816(acc[mt][nt], ah[mt], bb[nt]);
                    mma16816(acc[mt][nt], al[mt], bb[nt]);
                }
#pragma unroll
            for (int nt = 0; nt < 4; ++nt) {
                uint32_t off = (b_row + nt * 8) * ROWB + b_colb + kofs;
                ldsm_x2(bb[nt], sBl + off);
            }
#pragma unroll
            for (int mt = 0; mt < 4; ++mt)
#pragma unroll
                for (int nt = 0; nt < 4; ++nt)
                    mma16816(acc[mt][nt], ah[mt], bb[nt]);
        }
        __syncthreads();
    }

    const int er = lane >> 2;
    const int ec = (lane & 3) * 2;
#pragma unroll
    for (int mt = 0; mt < 4; ++mt) {
        const int row0 = bm + wm * 64 + mt * 16 + er;
#pragma unroll
        for (int nt = 0; nt < 4; ++nt) {
            const int col = bn + wn * 32 + nt * 8 + ec;
            float2 v0 = {acc[mt][nt][0], acc[mt][nt][1]};
            float2 v1 = {acc[mt][nt][2], acc[mt][nt][3]};
            *(float2*)(C + (size_t)row0 * N + col)       = v0;
            *(float2*)(C + (size_t)(row0 + 8) * N + col) = v1;
        }
    }
}

// ============================================================================
// RoPE tables + fused rope/split for fused QKV buffer
//   heads 0..31  : Q  -> rope -> qh/ql
//   heads 32..39 : K  -> rope -> kh/kl
//   heads 40..47 : V  -> plain split -> vh/vl
// ============================================================================
__global__ void rope_table(float* __restrict__ ct, float* __restrict__ st)
{
    int t = blockIdx.x * blockDim.x + threadIdx.x;
    if (t >= S_LEN * 32) return;
    int pos  = t >> 5;
    int pair = t & 31;
    float inv = (float)exp(-(double)pair * (9.210340371976184 / 32.0));
    float a = (float)pos * inv;
    float s, c;
    sincosf(a, &s, &c);
    ct[t] = c;
    st[t] = s;
}

__global__ void rope_split_v(const float* __restrict__ qkv,
                             const float* __restrict__ ct, const float* __restrict__ st,
                             __nv_bfloat16* __restrict__ qh, __nv_bfloat16* __restrict__ ql,
                             __nv_bfloat16* __restrict__ kh, __nv_bfloat16* __restrict__ kl,
                             __nv_bfloat16* __restrict__ vh, __nv_bfloat16* __restrict__ vl)
{
    const int TOT = MROWS * 48 * 32;
    int t = blockIdx.x * blockDim.x + threadIdx.x;
    if (t >= TOT) return;

    int pair = t & 31;
    int rest = t >> 5;
    int head = rest % 48;
    int row  = rest / 48;
    int pos  = row & (S_LEN - 1);

    const float* src;
    __nv_bfloat16 *H, *L;
    size_t obase;
    bool do_rope;
    if (head < 32) {
        src = qkv + (size_t)row * QKVN + head * HDIM;
        obase = (size_t)row * HID + head * HDIM;
        H = qh; L = ql; do_rope = true;
    } else if (head < 40) {
        src = qkv + (size_t)row * QKVN + HID + (head - 32) * HDIM;
        obase = (size_t)row * KVDIM + (head - 32) * HDIM;
        H = kh; L = kl; do_rope = true;
    } else {
        src = qkv + (size_t)row * QKVN + HID + KVDIM + (head - 40) * HDIM;
        obase = (size_t)row * KVDIM + (head - 40) * HDIM;
        H = vh; L = vl; do_rope = false;
    }

    float x0 = src[pair];
    float x1 = src[pair + 32];
    float y0 = x0, y1 = x1;
    if (do_rope) {
        float cv = ct[pos * 32 + pair];
        float sv = st[pos * 32 + pair];
        y0 = x0 * cv - x1 * sv;
        y1 = x1 * cv + x0 * sv;
    }

    __nv_bfloat16 h0 = __float2bfloat16(y0);
    __nv_bfloat16 h1 = __float2bfloat16(y1);
    H[obase + pair]      = h0;
    H[obase + pair + 32] = h1;
    L[obase + pair]      = __float2bfloat16(y0 - __bfloat162float(h0));
    L[obase + pair + 32] = __float2bfloat16(y1 - __bfloat162float(h1));
}

// ============================================================================
// Tensor-core flash attention (bf16 hi/lo, fp32 accum, causal)
// q-tile 128 rows, 8 warps x 16 rows; K/V 64x64 tiles double-buffered.
// ============================================================================
#define AT_ROWB 144
#define AT_TILE (64 * AT_ROWB)                // 9216 B
#define AT_QTILE (128 * AT_ROWB)              // 18432 B
#define ATTN_SMEM (2 * AT_QTILE + 8 * AT_TILE)   // 110592 B

__global__ __launch_bounds__(256) void attn_mma(
    const __nv_bfloat16* __restrict__ qh, const __nv_bfloat16* __restrict__ ql,
    const __nv_bfloat16* __restrict__ kh, const __nv_bfloat16* __restrict__ kl,
    const __nv_bfloat16* __restrict__ vh, const __nv_bfloat16* __restrict__ vl,
    __nv_bfloat16* __restrict__ oh, __nv_bfloat16* __restrict__ ol)
{
    extern __shared__ char smem[];
    const uint32_t sbase = smem_to_u32(smem);

    const int qt  = blockIdx.x;
    const int h   = blockIdx.y;
    const int b   = blockIdx.z;
    const int kvh = h >> 2;
    const int q0  = qt << 7;            // 128-row q tile
    const int tid = threadIdx.x;
    const int warp = tid >> 5;
    const int lane = tid & 31;

    const uint32_t sQh = sbase;
    const uint32_t sQl = sbase + AT_QTILE;
    auto kvtile = [&](int buf, int t) -> uint32_t {
        return sbase + 2 * AT_QTILE + (buf * 4 + t) * AT_TILE;
    };

    // ---- Q loader: 256 threads, row = tid/2, 4 segs each of Qh and Ql ----
    {
        const int lrow = tid >> 1;
        const int lsg  = (tid & 1) * 4;
        const size_t grow = (size_t)(b * S_LEN + q0 + lrow) * HID + h * HDIM;
#pragma unroll
        for (int i = 0; i < 4; ++i) {
            int seg = lsg + i;
            uint32_t so = (uint32_t)(lrow * AT_ROWB + seg * 16);
            CP_ASYNC16(sQh + so, qh + grow + seg * 8);
            CP_ASYNC16(sQl + so, ql + grow + seg * 8);
        }
        CP_COMMIT();
    }

    // ---- KV loader: row = tid/4, 2 segs x 4 tiles ----
    const int krow = tid >> 2;
    const int ksg  = (tid & 3) * 2;
    auto issue_kv = [&](int kt, int buf) {
        const size_t grow = (size_t)(b * S_LEN + kt * 64 + krow) * KVDIM + kvh * HDIM;
        const uint32_t t0 = kvtile(buf, 0), t1 = kvtile(buf, 1);
        const uint32_t t2 = kvtile(buf, 2), t3 = kvtile(buf, 3);
#pragma unroll
        for (int i = 0; i < 2; ++i) {
            int seg = ksg + i;
            uint32_t so = (uint32_t)(krow * AT_ROWB + seg * 16);
            CP_ASYNC16(t0 + so, kh + grow + seg * 8);
            CP_ASYNC16(t1 + so, kl + grow + seg * 8);
            CP_ASYNC16(t2 + so, vh + grow + seg * 8);
            CP_ASYNC16(t3 + so, vl + grow + seg * 8);
        }
        CP_COMMIT();
    };

    issue_kv(0, 0);

    const uint32_t a_row  = (uint32_t)(warp * 16 + (lane & 15));
    const uint32_t a_colb = (uint32_t)((lane >> 4) * 16);
    const uint32_t kb_row = (uint32_t)(lane & 7);
    const uint32_t kb_sel = (uint32_t)(((lane >> 3) & 1) * 16);
    const uint32_t v_row  = (uint32_t)(lane & 15);

    const int er = lane >> 2;
    const int ec = (lane & 3) * 2;
    const int qg0 = q0 + warp * 16 + er;
    const int qg1 = qg0 + 8;

    uint32_t qhf[4][4], qlf[4][4];

    float o[8][4];
#pragma unroll
    for (int i = 0; i < 8; ++i)
#pragma unroll
        for (int c = 0; c < 4; ++c) o[i][c] = 0.f;
    float m0 = -INFINITY, m1 = -INFINITY, l0 = 0.f, l1 = 0.f;

    const int NT = 2 * qt + 2;     // number of 64-key tiles

    for (int kt = 0; kt < NT; ++kt) {
        const int buf = kt & 1;
        if (kt + 1 < NT) { issue_kv(kt + 1, buf ^ 1); CP_WAIT(1); }
        else             { CP_WAIT(0); }
        __syncthreads();

        if (kt == 0) {
#pragma unroll
            for (int ks = 0; ks < 4; ++ks) {
                uint32_t off = a_row * AT_ROWB + a_colb + ks * 32;
                ldsm_x4(qhf[ks], sQh + off);
                ldsm_x4(qlf[ks], sQl + off);
            }
        }

        // ---- S = Q K^T ----
        float s[8][4];
#pragma unroll
        for (int nt = 0; nt < 8; ++nt)
#pragma unroll
            for (int c = 0; c < 4; ++c) s[nt][c] = 0.f;

        const uint32_t sKh = kvtile(buf, 0), sKl = kvtile(buf, 1);
#pragma unroll
        for (int nt = 0; nt < 8; ++nt) {
#pragma unroll
            for (int ks = 0; ks < 4; ++ks) {
                uint32_t off = (nt * 8 + kb_row) * AT_ROWB + kb_sel + ks * 32;
                uint32_t kfh[2], kfl[2];
                ldsm_x2(kfh, sKh + off);
                ldsm_x2(kfl, sKl + off);
                mma16816(s[nt], qhf[ks], kfh);
                mma16816(s[nt], qhf[ks], kfl);
                mma16816(s[nt], qlf[ks], kfh);
            }
        }

        const int k0 = kt << 6;
#pragma unroll
        for (int nt = 0; nt < 8; ++nt)
#pragma unroll
            for (int c = 0; c < 4; ++c) s[nt][c] *= 0.125f;

        if (kt >= 2 * qt) {    // only the last two tiles can cross the diagonal
#pragma unroll
            for (int nt = 0; nt < 8; ++nt) {
                int kg = k0 + nt * 8 + ec;
                if (kg     > qg0) s[nt][0] = -INFINITY;
                if (kg + 1 > qg0) s[nt][1] = -INFINITY;
                if (kg     > qg1) s[nt][2] = -INFINITY;
                if (kg + 1 > qg1) s[nt][3] = -INFINITY;
            }
        }

        // ---- online softmax ----
        float mx0 = -INFINITY, mx1 = -INFINITY;
#pragma unroll
        for (int nt = 0; nt < 8; ++nt) {
            mx0 = fmaxf(mx0, fmaxf(s[nt][0], s[nt][1]));
            mx1 = fmaxf(mx1, fmaxf(s[nt][2], s[nt][3]));
        }
        mx0 = fmaxf(mx0, __shfl_xor_sync(0xffffffffu, mx0, 1));
        mx0 = fmaxf(mx0, __shfl_xor_sync(0xffffffffu, mx0, 2));
        mx1 = fmaxf(mx1, __shfl_xor_sync(0xffffffffu, mx1, 1));
        mx1 = fmaxf(mx1, __shfl_xor_sync(0xffffffffu, mx1, 2));

        float mn0 = fmaxf(m0, mx0), mn1 = fmaxf(m1, mx1);
        float cr0 = __expf(m0 - mn0), cr1 = __expf(m1 - mn1);

        float ls0 = 0.f, ls1 = 0.f;
#pragma unroll
        for (int nt = 0; nt < 8; ++nt) {
            s[nt][0] = __expf(s[nt][0] - mn0);
            s[nt][1] = __expf(s[nt][1] - mn0);
            s[nt][2] = __expf(s[nt][2] - mn1);
            s[nt][3] = __expf(s[nt][3] - mn1);
            ls0 += s[nt][0] + s[nt][1];
            ls1 += s[nt][2] + s[nt][3];
        }
        ls0 += __shfl_xor_sync(0xffffffffu, ls0, 1);
        ls0 += __shfl_xor_sync(0xffffffffu, ls0, 2);
        ls1 += __shfl_xor_sync(0xffffffffu, ls1, 1);
        ls1 += __shfl_xor_sync(0xffffffffu, ls1, 2);
        l0 = l0 * cr0 + ls0;
        l1 = l1 * cr1 + ls1;
        m0 = mn0; m1 = mn1;

#pragma unroll
        for (int nt = 0; nt < 8; ++nt) {
            o[nt][0] *= cr0; o[nt][1] *= cr0;
            o[nt][2] *= cr1; o[nt][3] *= cr1;
        }

        // ---- pack P -> A fragments ----
        uint32_t ph[4][4], pl[4][4];
#pragma unroll
        for (int ks = 0; ks < 4; ++ks) {
            pack_hilo(s[2 * ks][0],     s[2 * ks][1],     ph[ks][0], pl[ks][0]);
            pack_hilo(s[2 * ks][2],     s[2 * ks][3],     ph[ks][1], pl[ks][1]);
            pack_hilo(s[2 * ks + 1][0], s[2 * ks + 1][1], ph[ks][2], pl[ks][2]);
            pack_hilo(s[2 * ks + 1][2], s[2 * ks + 1][3], ph[ks][3], pl[ks][3]);
        }

        // ---- O += P V ----
        const uint32_t sVh = kvtile(buf, 2), sVl = kvtile(buf, 3);
#pragma unroll
        for (int nt = 0; nt < 8; ++nt) {
#pragma unroll
            for (int ks = 0; ks < 4; ++ks) {
                uint32_t off = (ks * 16 + v_row) * AT_ROWB + nt * 16;
                uint32_t vfh[2], vfl[2];
                ldsm_x2_trans(vfh, sVh + off);
                ldsm_x2_trans(vfl, sVl + off);
                mma16816(o[nt], ph[ks], vfh);
                mma16816(o[nt], ph[ks], vfl);
                mma16816(o[nt], pl[ks], vfh);
            }
        }
        __syncthreads();
    }

    // ---- epilogue ----
    const float il0 = 1.f / l0, il1 = 1.f / l1;
    const size_t row0 = (size_t)(b * S_LEN + qg0);
    const size_t row1 = (size_t)(b * S_LEN + qg1);
#pragma unroll
    for (int nt = 0; nt < 8; ++nt) {
        const int col = h * HDIM + nt * 8 + ec;
        uint32_t hi, lo;
        pack_hilo(o[nt][0] * il0, o[nt][1] * il0, hi, lo);
        *(uint32_t*)(oh + row0 * HID + col) = hi;
        *(uint32_t*)(ol + row0 * HID + col) = lo;
        pack_hilo(o[nt][2] * il1, o[nt][3] * il1, hi, lo);
        *(uint32_t*)(oh + row1 * HID + col) = hi;
        *(uint32_t*)(ol + row1 * HID + col) = lo;
    }
}

// ============================================================================
// kernel_launch
// ============================================================================
extern "C" void kernel_launch(void* const* d_in, const int* in_sizes, int n_in,
                              void* d_out, int out_size)
{
    (void)in_sizes; (void)n_in; (void)out_size;
    const float* x  = (const float*)d_in[0];
    const float* Wq = (const float*)d_in[1];
    const float* Wk = (const float*)d_in[2];
    const float* Wv = (const float*)d_in[3];
    const float* Wo = (const float*)d_in[4];
    float* out = (float*)d_out;

    float *qkv, *rc, *rs;
    cudaGetSymbolAddress((void**)&qkv, g_qkv);
    cudaGetSymbolAddress((void**)&rc, g_rc);
    cudaGetSymbolAddress((void**)&rs, g_rs);

    __nv_bfloat16 *xh, *xl, *w3h, *w3l, *woh, *wol, *ah, *al;
    __nv_bfloat16 *qhb, *qlb, *khb, *klb, *vhb, *vlb;
    cudaGetSymbolAddress((void**)&xh,  g_xh);
    cudaGetSymbolAddress((void**)&xl,  g_xl);
    cudaGetSymbolAddress((void**)&w3h, g_w3h);
    cudaGetSymbolAddress((void**)&w3l, g_w3l);
    cudaGetSymbolAddress((void**)&woh, g_woh);
    cudaGetSymbolAddress((void**)&wol, g_wol);
    cudaGetSymbolAddress((void**)&ah,  g_ah);
    cudaGetSymbolAddress((void**)&al,  g_al);
    cudaGetSymbolAddress((void**)&qhb, g_qh);
    cudaGetSymbolAddress((void**)&qlb, g_ql);
    cudaGetSymbolAddress((void**)&khb, g_kh);
    cudaGetSymbolAddress((void**)&klb, g_kl);
    cudaGetSymbolAddress((void**)&vhb, g_vh);
    cudaGetSymbolAddress((void**)&vlb, g_vl);

    cudaFuncSetAttribute(gemm_mma, cudaFuncAttributeMaxDynamicSharedMemorySize, GEMM_SMEM);
    cudaFuncSetAttribute(attn_mma, cudaFuncAttributeMaxDynamicSharedMemorySize, ATTN_SMEM);

    const int M = MROWS;
    const int nx = M * HID, nwq = HID * HID, nwk = KVDIM * HID;

    // launch 0: rope tables (independent)
    rope_table<<<(S_LEN * 32 + 255) / 256, 256>>>(rc, rs);

    // launches 1-4: splits (x, Wq, Wk, Wv -> packed W3)
    split_bf16<<<(nx  + 255) / 256, 256>>>(x,  xh, xl, nx);
    split_bf16<<<(nwq + 255) / 256, 256>>>(Wq, w3h,                      w3l,                      nwq);
    split_bf16<<<(nwk + 255) / 256, 256>>>(Wk, w3h + (size_t)HID * HID,  w3l + (size_t)HID * HID,  nwk);
    split_bf16<<<(nwk + 255) / 256, 256>>>(Wv, w3h + (size_t)(HID + KVDIM) * HID,
                                               w3l + (size_t)(HID + KVDIM) * HID, nwk);

    // launch 5: fused QKV projection  (ncu -s 5 captures this)
    gemm_mma<<<dim3(QKVN / BN, M / BM), 256, GEMM_SMEM>>>(xh, xl, w3h, w3l, qkv, M, QKVN, HID);

    // launch 6: rope + hi/lo conversion (Q,K) + V split
    const int rs_tot = M * 48 * 32;
    rope_split_v<<<(rs_tot + 255) / 256, 256>>>(qkv, rc, rs, qhb, qlb, khb, klb, vhb, vlb);

    // launch 7: causal flash attention (128-row q tiles)
    attn_mma<<<dim3(S_LEN / 128, NHEADS, BATCH), 256, ATTN_SMEM>>>(
        qhb, qlb, khb, klb, vhb, vlb, ah, al);

    // launches 8-9: Wo split + output projection
    split_bf16<<<(nwq + 255) / 256, 256>>>(Wo, woh, wol, nwq);
    gemm_mma<<<dim3(HID / BN, M / BM), 256, GEMM_SMEM>>>(ah, al, woh, wol, out, M, HID, HID);
}

// round 8
// speedup vs baseline: 5.6736x; 1.5477x over previous
#include <cuda_runtime.h>
#include <cuda_bf16.h>
#include <cuda_fp16.h>
#include <math.h>
#include <stdint.h>

#define S_LEN   2048
#define BATCH   2
#define HID     2048
#define NHEADS  32
#define KVHEADS 8
#define HDIM    64
#define MROWS   (BATCH * S_LEN)     // 4096
#define KVDIM   (KVHEADS * HDIM)    // 512
#define QKVN    (HID + 2 * KVDIM)   // 3072

// ---------------- scratch (static device globals; no allocations) ----------
__device__ float g_qkv[(size_t)MROWS * QKVN];      // fused QKV output (fp32)

__device__ __half g_xh [(size_t)MROWS * HID];      // x hi
__device__ __half g_xl [(size_t)MROWS * HID];      // x lo
__device__ __half g_w3 [(size_t)QKVN * HID];       // packed Wq|Wk|Wv (single fp16)
__device__ __half g_wo [(size_t)HID * HID];        // Wo (single fp16)
__device__ __half g_ah [(size_t)MROWS * HID];      // attention out hi
__device__ __half g_al [(size_t)MROWS * HID];      // attention out lo

__device__ __half g_qh [(size_t)MROWS * HID];      // rotated Q hi
__device__ __half g_ql [(size_t)MROWS * HID];      // rotated Q lo
__device__ __half g_k16[(size_t)MROWS * KVDIM];    // rotated K (single fp16)
__device__ __half g_v16[(size_t)MROWS * KVDIM];    // V (single fp16)

__device__ float g_rc[S_LEN * 32];
__device__ float g_rs[S_LEN * 32];

// ============================================================================
// PTX helpers (plain sm_103-safe)
// ============================================================================
__device__ __forceinline__ uint32_t smem_to_u32(const void* p) {
    uint32_t a;
    asm("{ .reg .u64 t; cvta.to.shared.u64 t, %1; cvt.u32.u64 %0, t; }"
        : "=r"(a) : "l"(p));
    return a;
}

#define CP_ASYNC16(smem, gmem) \
    asm volatile("cp.async.cg.shared.global [%0], [%1], 16;" \
                 :: "r"(smem), "l"(gmem) : "memory")
#define CP_COMMIT() asm volatile("cp.async.commit_group;" ::: "memory")
#define CP_WAIT(n)  asm volatile("cp.async.wait_group %0;" :: "n"(n) : "memory")

__device__ __forceinline__ void ldsm_x4(uint32_t* r, uint32_t addr) {
    asm volatile("ldmatrix.sync.aligned.m8n8.x4.shared.b16 {%0,%1,%2,%3}, [%4];"
        : "=r"(r[0]), "=r"(r[1]), "=r"(r[2]), "=r"(r[3]) : "r"(addr));
}
__device__ __forceinline__ void ldsm_x2(uint32_t* r, uint32_t addr) {
    asm volatile("ldmatrix.sync.aligned.m8n8.x2.shared.b16 {%0,%1}, [%2];"
        : "=r"(r[0]), "=r"(r[1]) : "r"(addr));
}
__device__ __forceinline__ void ldsm_x2_trans(uint32_t* r, uint32_t addr) {
    asm volatile("ldmatrix.sync.aligned.m8n8.x2.trans.shared.b16 {%0,%1}, [%2];"
        : "=r"(r[0]), "=r"(r[1]) : "r"(addr));
}

// D(f32) += A(fp16) * B(fp16), m16n8k16
__device__ __forceinline__ void mma16816(float* d, const uint32_t* a, const uint32_t* b) {
    asm volatile(
        "mma.sync.aligned.m16n8k16.row.col.f32.f16.f16.f32 "
        "{%0,%1,%2,%3}, {%4,%5,%6,%7}, {%8,%9}, {%0,%1,%2,%3};"
        : "+f"(d[0]), "+f"(d[1]), "+f"(d[2]), "+f"(d[3])
        : "r"(a[0]), "r"(a[1]), "r"(a[2]), "r"(a[3]), "r"(b[0]), "r"(b[1]));
}

// pack two floats into fp16x2 (hi) plus residual fp16x2 (lo)
__device__ __forceinline__ void pack_hilo(float a, float b, uint32_t& hi, uint32_t& lo) {
    __half ha = __float2half_rn(a);
    __half hb = __float2half_rn(b);
    __half2 H; H.x = ha; H.y = hb;
    hi = *reinterpret_cast<uint32_t*>(&H);
    __half2 L;
    L.x = __float2half_rn(a - __half2float(ha));
    L.y = __float2half_rn(b - __half2float(hb));
    lo = *reinterpret_cast<uint32_t*>(&L);
}

// ============================================================================
// fp32 -> fp16 hi/lo split, and fp32 -> fp16 convert
// ============================================================================
__global__ void split_fp16(const float* __restrict__ in,
                           __half* __restrict__ hi, __half* __restrict__ lo, int n)
{
    int i = blockIdx.x * blockDim.x + threadIdx.x;
    if (i >= n) return;
    float v = in[i];
    __half h = __float2half_rn(v);
    hi[i] = h;
    lo[i] = __float2half_rn(v - __half2float(h));
}

__global__ void conv_fp16(const float* __restrict__ in, __half* __restrict__ out, int n)
{
    int i = blockIdx.x * blockDim.x + threadIdx.x;
    if (i >= n) return;
    out[i] = __float2half_rn(in[i]);
}

// ============================================================================
// fp16 2-term GEMM via mma.sync:  C[M,N] = A[M,K] @ B[N,K]^T
//   A = Ah + Al (fp16 hi/lo), B single fp16.  D = Ah*B + Al*B.
// 128x128 CTA tile, BK=32, 8 warps (2x4), cp.async double-buffered.
// ============================================================================
#define BM 128
#define BN 128
#define BK 32
#define ROWB   80
#define ASZ    (128 * ROWB)
#define STAGE  (3 * ASZ)                 // Ah, Al, B
#define GEMM_SMEM (2 * STAGE)            // 61440 B

__global__ __launch_bounds__(256) void gemm_mma(
    const __half* __restrict__ Ah, const __half* __restrict__ Al,
    const __half* __restrict__ B,
    float* __restrict__ C, int M, int N, int K)
{
    extern __shared__ char smem[];
    const uint32_t sbase = smem_to_u32(smem);

    const int tid  = threadIdx.x;
    const int wid  = tid >> 5;
    const int lane = tid & 31;
    const int wm   = wid >> 2;
    const int wn   = wid & 3;
    const int bm   = blockIdx.y * BM;
    const int bn   = blockIdx.x * BN;

    const __half* gAh = Ah + (size_t)bm * K;
    const __half* gAl = Al + (size_t)bm * K;
    const __half* gB  = B  + (size_t)bn * K;

    const int NC = K / BK;

    const int lr  = tid >> 2;
    const int lsg = tid & 3;
    auto issue = [&](int kc, int buf) {
        const uint32_t sb = sbase + buf * STAGE;
        const size_t kofs = (size_t)kc * BK + lsg * 8;
#pragma unroll
        for (int t = 0; t < 2; ++t) {
            int r = lr + t * 64;
            uint32_t so = (uint32_t)(r * ROWB + lsg * 16);
            size_t g = (size_t)r * K + kofs;
            CP_ASYNC16(sb + so,           gAh + g);
            CP_ASYNC16(sb + ASZ + so,     gAl + g);
            CP_ASYNC16(sb + 2 * ASZ + so, gB  + g);
        }
        CP_COMMIT();
    };

    float acc[4][4][4];
#pragma unroll
    for (int i = 0; i < 4; ++i)
#pragma unroll
        for (int j = 0; j < 4; ++j)
#pragma unroll
            for (int c = 0; c < 4; ++c) acc[i][j][c] = 0.f;

    const uint32_t a_row  = (uint32_t)(wm * 64 + (lane & 15));
    const uint32_t a_colb = (uint32_t)((lane >> 4) * 16);
    const uint32_t b_row  = (uint32_t)(wn * 32 + (lane & 7));
    const uint32_t b_colb = (uint32_t)(((lane >> 3) & 1) * 16);

    issue(0, 0);

    for (int kt = 0; kt < NC; ++kt) {
        const int buf = kt & 1;
        if (kt + 1 < NC) { issue(kt + 1, buf ^ 1); CP_WAIT(1); }
        else             { CP_WAIT(0); }
        __syncthreads();

        const uint32_t sAh = sbase + buf * STAGE;
        const uint32_t sAl = sAh + ASZ;
        const uint32_t sB  = sAh + 2 * ASZ;

#pragma unroll
        for (int ks = 0; ks < 2; ++ks) {
            const uint32_t kofs = ks * 32;

            uint32_t ah[4][4], al[4][4], bb[4][2];
#pragma unroll
            for (int mt = 0; mt < 4; ++mt) {
                uint32_t off = (a_row + mt * 16) * ROWB + a_colb + kofs;
                ldsm_x4(ah[mt], sAh + off);
                ldsm_x4(al[mt], sAl + off);
            }
#pragma unroll
            for (int nt = 0; nt < 4; ++nt) {
                uint32_t off = (b_row + nt * 8) * ROWB + b_colb + kofs;
                ldsm_x2(bb[nt], sB + off);
            }
#pragma unroll
            for (int mt = 0; mt < 4; ++mt)
#pragma unroll
                for (int nt = 0; nt < 4; ++nt) {
                    mma16816(acc[mt][nt], ah[mt], bb[nt]);
                    mma16816(acc[mt][nt], al[mt], bb[nt]);
                }
        }
        __syncthreads();
    }

    const int er = lane >> 2;
    const int ec = (lane & 3) * 2;
#pragma unroll
    for (int mt = 0; mt < 4; ++mt) {
        const int row0 = bm + wm * 64 + mt * 16 + er;
#pragma unroll
        for (int nt = 0; nt < 4; ++nt) {
            const int col = bn + wn * 32 + nt * 8 + ec;
            float2 v0 = {acc[mt][nt][0], acc[mt][nt][1]};
            float2 v1 = {acc[mt][nt][2], acc[mt][nt][3]};
            *(float2*)(C + (size_t)row0 * N + col)       = v0;
            *(float2*)(C + (size_t)(row0 + 8) * N + col) = v1;
        }
    }
}

// ============================================================================
// RoPE tables + fused rope/split over fused QKV buffer
//   heads 0..31  : Q -> rope -> qh/ql (fp16 hi/lo)
//   heads 32..39 : K -> rope -> k16 (single fp16)
//   heads 40..47 : V -> k16-style single fp16 (no rope)
// ============================================================================
__global__ void rope_table(float* __restrict__ ct, float* __restrict__ st)
{
    int t = blockIdx.x * blockDim.x + threadIdx.x;
    if (t >= S_LEN * 32) return;
    int pos  = t >> 5;
    int pair = t & 31;
    float inv = (float)exp(-(double)pair * (9.210340371976184 / 32.0));
    float a = (float)pos * inv;
    float s, c;
    sincosf(a, &s, &c);
    ct[t] = c;
    st[t] = s;
}

__global__ void rope_split_v(const float* __restrict__ qkv,
                             const float* __restrict__ ct, const float* __restrict__ st,
                             __half* __restrict__ qh, __half* __restrict__ ql,
                             __half* __restrict__ k16, __half* __restrict__ v16)
{
    const int TOT = MROWS * 48 * 32;
    int t = blockIdx.x * blockDim.x + threadIdx.x;
    if (t >= TOT) return;

    int pair = t & 31;
    int rest = t >> 5;
    int head = rest % 48;
    int row  = rest / 48;
    int pos  = row & (S_LEN - 1);

    if (head < 32) {                 // Q: rope + hi/lo split
        const float* src = qkv + (size_t)row * QKVN + head * HDIM;
        size_t obase = (size_t)row * HID + head * HDIM;
        float cv = ct[pos * 32 + pair];
        float sv = st[pos * 32 + pair];
        float x0 = src[pair], x1 = src[pair + 32];
        float y0 = x0 * cv - x1 * sv;
        float y1 = x1 * cv + x0 * sv;
        __half h0 = __float2half_rn(y0);
        __half h1 = __float2half_rn(y1);
        qh[obase + pair]      = h0;
        qh[obase + pair + 32] = h1;
        ql[obase + pair]      = __float2half_rn(y0 - __half2float(h0));
        ql[obase + pair + 32] = __float2half_rn(y1 - __half2float(h1));
    } else if (head < 40) {          // K: rope + single fp16
        const float* src = qkv + (size_t)row * QKVN + HID + (head - 32) * HDIM;
        size_t obase = (size_t)row * KVDIM + (head - 32) * HDIM;
        float cv = ct[pos * 32 + pair];
        float sv = st[pos * 32 + pair];
        float x0 = src[pair], x1 = src[pair + 32];
        k16[obase + pair]      = __float2half_rn(x0 * cv - x1 * sv);
        k16[obase + pair + 32] = __float2half_rn(x1 * cv + x0 * sv);
    } else {                         // V: single fp16
        const float* src = qkv + (size_t)row * QKVN + HID + KVDIM + (head - 40) * HDIM;
        size_t obase = (size_t)row * KVDIM + (head - 40) * HDIM;
        v16[obase + pair]      = __float2half_rn(src[pair]);
        v16[obase + pair + 32] = __float2half_rn(src[pair + 32]);
    }
}

// ============================================================================
// Tensor-core flash attention (fp16 2-term, fp32 accum, causal)
// q-tile 128 rows, 8 warps x 16 rows; K/V 64x64 single-fp16 tiles, dbl-buffered.
// ============================================================================
#define AT_ROWB 144
#define AT_TILE (64 * AT_ROWB)                   // 9216 B
#define AT_QTILE (128 * AT_ROWB)                 // 18432 B
#define ATTN_SMEM (2 * AT_QTILE + 4 * AT_TILE)   // 73728 B

__global__ __launch_bounds__(256) void attn_mma(
    const __half* __restrict__ qh, const __half* __restrict__ ql,
    const __half* __restrict__ k16, const __half* __restrict__ v16,
    __half* __restrict__ oh, __half* __restrict__ ol)
{
    extern __shared__ char smem[];
    const uint32_t sbase = smem_to_u32(smem);

    const int qt  = blockIdx.x;
    const int h   = blockIdx.y;
    const int b   = blockIdx.z;
    const int kvh = h >> 2;
    const int q0  = qt << 7;
    const int tid = threadIdx.x;
    const int warp = tid >> 5;
    const int lane = tid & 31;

    const uint32_t sQh = sbase;
    const uint32_t sQl = sbase + AT_QTILE;
    auto kvtile = [&](int buf, int t) -> uint32_t {   // t: 0=K, 1=V
        return sbase + 2 * AT_QTILE + (buf * 2 + t) * AT_TILE;
    };

    // ---- Q loader ----
    {
        const int lrow = tid >> 1;
        const int lsg  = (tid & 1) * 4;
        const size_t grow = (size_t)(b * S_LEN + q0 + lrow) * HID + h * HDIM;
#pragma unroll
        for (int i = 0; i < 4; ++i) {
            int seg = lsg + i;
            uint32_t so = (uint32_t)(lrow * AT_ROWB + seg * 16);
            CP_ASYNC16(sQh + so, qh + grow + seg * 8);
            CP_ASYNC16(sQl + so, ql + grow + seg * 8);
        }
        CP_COMMIT();
    }

    // ---- KV loader: row = tid/4, 2 segs x 2 tiles ----
    const int krow = tid >> 2;
    const int ksg  = (tid & 3) * 2;
    auto issue_kv = [&](int kt, int buf) {
        const size_t grow = (size_t)(b * S_LEN + kt * 64 + krow) * KVDIM + kvh * HDIM;
        const uint32_t t0 = kvtile(buf, 0), t1 = kvtile(buf, 1);
#pragma unroll
        for (int i = 0; i < 2; ++i) {
            int seg = ksg + i;
            uint32_t so = (uint32_t)(krow * AT_ROWB + seg * 16);
            CP_ASYNC16(t0 + so, k16 + grow + seg * 8);
            CP_ASYNC16(t1 + so, v16 + grow + seg * 8);
        }
        CP_COMMIT();
    };

    issue_kv(0, 0);

    const uint32_t a_row  = (uint32_t)(warp * 16 + (lane & 15));
    const uint32_t a_colb = (uint32_t)((lane >> 4) * 16);
    const uint32_t kb_row = (uint32_t)(lane & 7);
    const uint32_t kb_sel = (uint32_t)(((lane >> 3) & 1) * 16);
    const uint32_t v_row  = (uint32_t)(lane & 15);

    const int er = lane >> 2;
    const int ec = (lane & 3) * 2;
    const int qg0 = q0 + warp * 16 + er;
    const int qg1 = qg0 + 8;

    uint32_t qhf[4][4], qlf[4][4];

    float o[8][4];
#pragma unroll
    for (int i = 0; i < 8; ++i)
#pragma unroll
        for (int c = 0; c < 4; ++c) o[i][c] = 0.f;
    float m0 = -INFINITY, m1 = -INFINITY, l0 = 0.f, l1 = 0.f;

    const int NT = 2 * qt + 2;

    for (int kt = 0; kt < NT; ++kt) {
        const int buf = kt & 1;
        if (kt + 1 < NT) { issue_kv(kt + 1, buf ^ 1); CP_WAIT(1); }
        else             { CP_WAIT(0); }
        __syncthreads();

        if (kt == 0) {
#pragma unroll
            for (int ks = 0; ks < 4; ++ks) {
                uint32_t off = a_row * AT_ROWB + a_colb + ks * 32;
                ldsm_x4(qhf[ks], sQh + off);
                ldsm_x4(qlf[ks], sQl + off);
            }
        }

        // ---- S = Q K^T (2-term) ----
        float s[8][4];
#pragma unroll
        for (int nt = 0; nt < 8; ++nt)
#pragma unroll
            for (int c = 0; c < 4; ++c) s[nt][c] = 0.f;

        const uint32_t sK = kvtile(buf, 0);
#pragma unroll
        for (int nt = 0; nt < 8; ++nt) {
#pragma unroll
            for (int ks = 0; ks < 4; ++ks) {
                uint32_t off = (nt * 8 + kb_row) * AT_ROWB + kb_sel + ks * 32;
                uint32_t kf[2];
                ldsm_x2(kf, sK + off);
                mma16816(s[nt], qhf[ks], kf);
                mma16816(s[nt], qlf[ks], kf);
            }
        }

        const int k0 = kt << 6;
#pragma unroll
        for (int nt = 0; nt < 8; ++nt)
#pragma unroll
            for (int c = 0; c < 4; ++c) s[nt][c] *= 0.125f;

        if (kt >= 2 * qt) {
#pragma unroll
            for (int nt = 0; nt < 8; ++nt) {
                int kg = k0 + nt * 8 + ec;
                if (kg     > qg0) s[nt][0] = -INFINITY;
                if (kg + 1 > qg0) s[nt][1] = -INFINITY;
                if (kg     > qg1) s[nt][2] = -INFINITY;
                if (kg + 1 > qg1) s[nt][3] = -INFINITY;
            }
        }

        // ---- online softmax ----
        float mx0 = -INFINITY, mx1 = -INFINITY;
#pragma unroll
        for (int nt = 0; nt < 8; ++nt) {
            mx0 = fmaxf(mx0, fmaxf(s[nt][0], s[nt][1]));
            mx1 = fmaxf(mx1, fmaxf(s[nt][2], s[nt][3]));
        }
        mx0 = fmaxf(mx0, __shfl_xor_sync(0xffffffffu, mx0, 1));
        mx0 = fmaxf(mx0, __shfl_xor_sync(0xffffffffu, mx0, 2));
        mx1 = fmaxf(mx1, __shfl_xor_sync(0xffffffffu, mx1, 1));
        mx1 = fmaxf(mx1, __shfl_xor_sync(0xffffffffu, mx1, 2));

        float mn0 = fmaxf(m0, mx0), mn1 = fmaxf(m1, mx1);
        float cr0 = __expf(m0 - mn0), cr1 = __expf(m1 - mn1);

        float ls0 = 0.f, ls1 = 0.f;
#pragma unroll
        for (int nt = 0; nt < 8; ++nt) {
            s[nt][0] = __expf(s[nt][0] - mn0);
            s[nt][1] = __expf(s[nt][1] - mn0);
            s[nt][2] = __expf(s[nt][2] - mn1);
            s[nt][3] = __expf(s[nt][3] - mn1);
            ls0 += s[nt][0] + s[nt][1];
            ls1 += s[nt][2] + s[nt][3];
        }
        ls0 += __shfl_xor_sync(0xffffffffu, ls0, 1);
        ls0 += __shfl_xor_sync(0xffffffffu, ls0, 2);
        ls1 += __shfl_xor_sync(0xffffffffu, ls1, 1);
        ls1 += __shfl_xor_sync(0xffffffffu, ls1, 2);
        l0 = l0 * cr0 + ls0;
        l1 = l1 * cr1 + ls1;
        m0 = mn0; m1 = mn1;

#pragma unroll
        for (int nt = 0; nt < 8; ++nt) {
            o[nt][0] *= cr0; o[nt][1] *= cr0;
            o[nt][2] *= cr1; o[nt][3] *= cr1;
        }

        // ---- pack P -> fp16 hi/lo A fragments ----
        uint32_t ph[4][4], pl[4][4];
#pragma unroll
        for (int ks = 0; ks < 4; ++ks) {
            pack_hilo(s[2 * ks][0],     s[2 * ks][1],     ph[ks][0], pl[ks][0]);
            pack_hilo(s[2 * ks][2],     s[2 * ks][3],     ph[ks][1], pl[ks][1]);
            pack_hilo(s[2 * ks + 1][0], s[2 * ks + 1][1], ph[ks][2], pl[ks][2]);
            pack_hilo(s[2 * ks + 1][2], s[2 * ks + 1][3], ph[ks][3], pl[ks][3]);
        }

        // ---- O += P V (2-term) ----
        const uint32_t sV = kvtile(buf, 1);
#pragma unroll
        for (int nt = 0; nt < 8; ++nt) {
#pragma unroll
            for (int ks = 0; ks < 4; ++ks) {
                uint32_t off = (ks * 16 + v_row) * AT_ROWB + nt * 16;
                uint32_t vf[2];
                ldsm_x2_trans(vf, sV + off);
                mma16816(o[nt], ph[ks], vf);
                mma16816(o[nt], pl[ks], vf);
            }
        }
        __syncthreads();
    }

    // ---- epilogue: O/l -> fp16 hi/lo output ----
    const float il0 = 1.f / l0, il1 = 1.f / l1;
    const size_t row0 = (size_t)(b * S_LEN + qg0);
    const size_t row1 = (size_t)(b * S_LEN + qg1);
#pragma unroll
    for (int nt = 0; nt < 8; ++nt) {
        const int col = h * HDIM + nt * 8 + ec;
        uint32_t hi, lo;
        pack_hilo(o[nt][0] * il0, o[nt][1] * il0, hi, lo);
        *(uint32_t*)(oh + row0 * HID + col) = hi;
        *(uint32_t*)(ol + row0 * HID + col) = lo;
        pack_hilo(o[nt][2] * il1, o[nt][3] * il1, hi, lo);
        *(uint32_t*)(oh + row1 * HID + col) = hi;
        *(uint32_t*)(ol + row1 * HID + col) = lo;
    }
}

// ============================================================================
// kernel_launch
// ============================================================================
extern "C" void kernel_launch(void* const* d_in, const int* in_sizes, int n_in,
                              void* d_out, int out_size)
{
    (void)in_sizes; (void)n_in; (void)out_size;
    const float* x  = (const float*)d_in[0];
    const float* Wq = (const float*)d_in[1];
    const float* Wk = (const float*)d_in[2];
    const float* Wv = (const float*)d_in[3];
    const float* Wo = (const float*)d_in[4];
    float* out = (float*)d_out;

    float *qkv, *rc, *rs;
    cudaGetSymbolAddress((void**)&qkv, g_qkv);
    cudaGetSymbolAddress((void**)&rc, g_rc);
    cudaGetSymbolAddress((void**)&rs, g_rs);

    __half *xh, *xl, *w3, *wo, *ah, *al, *qhb, *qlb, *k16, *v16;
    cudaGetSymbolAddress((void**)&xh,  g_xh);
    cudaGetSymbolAddress((void**)&xl,  g_xl);
    cudaGetSymbolAddress((void**)&w3,  g_w3);
    cudaGetSymbolAddress((void**)&wo,  g_wo);
    cudaGetSymbolAddress((void**)&ah,  g_ah);
    cudaGetSymbolAddress((void**)&al,  g_al);
    cudaGetSymbolAddress((void**)&qhb, g_qh);
    cudaGetSymbolAddress((void**)&qlb, g_ql);
    cudaGetSymbolAddress((void**)&k16, g_k16);
    cudaGetSymbolAddress((void**)&v16, g_v16);

    cudaFuncSetAttribute(gemm_mma, cudaFuncAttributeMaxDynamicSharedMemorySize, GEMM_SMEM);
    cudaFuncSetAttribute(attn_mma, cudaFuncAttributeMaxDynamicSharedMemorySize, ATTN_SMEM);

    const int M = MROWS;
    const int nx = M * HID, nwq = HID * HID, nwk = KVDIM * HID;

    // launch 0: rope tables
    rope_table<<<(S_LEN * 32 + 255) / 256, 256>>>(rc, rs);

    // launches 1-4: x split + weight converts (packed W3)
    split_fp16<<<(nx + 255) / 256, 256>>>(x, xh, xl, nx);
    conv_fp16<<<(nwq + 255) / 256, 256>>>(Wq, w3, nwq);
    conv_fp16<<<(nwk + 255) / 256, 256>>>(Wk, w3 + (size_t)HID * HID, nwk);
    conv_fp16<<<(nwk + 255) / 256, 256>>>(Wv, w3 + (size_t)(HID + KVDIM) * HID, nwk);

    // launch 5: fused QKV projection
    gemm_mma<<<dim3(QKVN / BN, M / BM), 256, GEMM_SMEM>>>(xh, xl, w3, qkv, M, QKVN, HID);

    // launch 6: rope + fp16 conversion
    const int rs_tot = M * 48 * 32;
    rope_split_v<<<(rs_tot + 255) / 256, 256>>>(qkv, rc, rs, qhb, qlb, k16, v16);

    // launch 7: causal flash attention
    attn_mma<<<dim3(S_LEN / 128, NHEADS, BATCH), 256, ATTN_SMEM>>>(
        qhb, qlb, k16, v16, ah, al);

    // launches 8-9: Wo convert + output projection
    conv_fp16<<<(nwq + 255) / 256, 256>>>(Wo, wo, nwq);
    gemm_mma<<<dim3(HID / BN, M / BM), 256, GEMM_SMEM>>>(ah, al, wo, out, M, HID, HID);
}